// round 1
// baseline (speedup 1.0000x reference)
#include <cuda_runtime.h>
#include <math.h>

// Problem constants
#define BB   2048
#define TT   32
#define BT   65536        // BB*TT
#define DIN_ 1024
#define DH_  64
#define HH   512
#define G4   2048         // 4*H
#define KIN  576          // DH + H
#define AA   64

typedef unsigned long long u64;

// ---------------- scratch (device globals; no allocations allowed) ----------------
__device__ float g_mu1[BT];
__device__ float g_rs1[BT];
__device__ float g_x[BT * DH_];                 // after LN1+dense+LN2+relu  [B*T, 64]
__device__ float g_hs[2][TT * BB * HH];         // unmasked h per step, per dir (plane-major [t][b][n])
__device__ float g_c[2][BB * HH];               // cell state per dir
__device__ float g_hcat[BB * TT * 2 * HH];      // masked concat output [b][t][1024]
__device__ float g_mu3[BB];
__device__ float g_rs3[BB];

// ---------------- helpers ----------------
__device__ __forceinline__ u64 pk2(float lo, float hi) {
    u64 r; asm("mov.b64 %0, {%1, %2};" : "=l"(r) : "f"(lo), "f"(hi)); return r;
}
__device__ __forceinline__ float2 upk2(u64 v) {
    float2 f; asm("mov.b64 {%0, %1}, %2;" : "=f"(f.x), "=f"(f.y) : "l"(v)); return f;
}
__device__ __forceinline__ void fma2(u64 &d, u64 a, u64 b) {
    asm("fma.rn.f32x2 %0, %1, %2, %0;" : "+l"(d) : "l"(a), "l"(b));
}
__device__ __forceinline__ float sigf(float x) { return 1.0f / (1.0f + expf(-x)); }

// ---------------- K0: per-row mean / rstd of ud (LN1 stats) ----------------
__global__ void k0_rowstats(const float* __restrict__ ud) {
    int row = blockIdx.x * 8 + threadIdx.y;      // blockDim = (32, 8)
    const float4* p = (const float4*)(ud + (size_t)row * DIN_);
    float s = 0.f, q = 0.f;
    for (int i = threadIdx.x; i < DIN_ / 4; i += 32) {
        float4 v = p[i];
        s += v.x + v.y + v.z + v.w;
        q += v.x * v.x + v.y * v.y + v.z * v.z + v.w * v.w;
    }
    #pragma unroll
    for (int o = 16; o; o >>= 1) {
        s += __shfl_down_sync(0xffffffffu, s, o);
        q += __shfl_down_sync(0xffffffffu, q, o);
    }
    if (threadIdx.x == 0) {
        float mu = s / (float)DIN_;
        float var = q / (float)DIN_ - mu * mu;
        g_mu1[row] = mu;
        g_rs1[row] = rsqrtf(var + 1e-12f);
    }
}

// ---------------- K1: LN1 -> dense(1024x64) -> LN2 -> relu  (BM=128, BN=64, BK=16) ----------------
__global__ void k1_dense(const float* __restrict__ ud,
                         const float* __restrict__ g1, const float* __restrict__ b1,
                         const float* __restrict__ Wd, const float* __restrict__ bd,
                         const float* __restrict__ g2, const float* __restrict__ b2) {
    __shared__ float As[16][132];
    __shared__ float Bs[16][64];
    __shared__ float buf[128][65];
    __shared__ float smu[128], srs[128];

    int tid = threadIdx.x;
    int bx = blockIdx.x;
    int ty = tid >> 4, tx = tid & 15;            // ty: 8-row group, tx: 4-col group

    float acc[8][4];
    #pragma unroll
    for (int r = 0; r < 8; r++)
        #pragma unroll
        for (int j = 0; j < 4; j++) acc[r][j] = 0.f;

    #pragma unroll 1
    for (int kt = 0; kt < DIN_; kt += 16) {
        // A tile: 128 rows x 16 k, normalized (LN1) on load
        #pragma unroll
        for (int it = 0; it < 2; it++) {
            int v = tid + it * 256;              // 512 float4
            int r = v >> 2, q = (v & 3) * 4;
            int gr = bx * 128 + r;
            float4 val = *(const float4*)(ud + (size_t)gr * DIN_ + kt + q);
            float mu = g_mu1[gr], rs = g_rs1[gr];
            As[q + 0][r] = (val.x - mu) * rs * g1[kt + q + 0] + b1[kt + q + 0];
            As[q + 1][r] = (val.y - mu) * rs * g1[kt + q + 1] + b1[kt + q + 1];
            As[q + 2][r] = (val.z - mu) * rs * g1[kt + q + 2] + b1[kt + q + 2];
            As[q + 3][r] = (val.w - mu) * rs * g1[kt + q + 3] + b1[kt + q + 3];
        }
        // B tile: 16 x 64
        {
            int k = tid >> 4, c0 = (tid & 15) * 4;
            float4 w = *(const float4*)(Wd + (size_t)(kt + k) * 64 + c0);
            Bs[k][c0 + 0] = w.x; Bs[k][c0 + 1] = w.y; Bs[k][c0 + 2] = w.z; Bs[k][c0 + 3] = w.w;
        }
        __syncthreads();
        #pragma unroll
        for (int k = 0; k < 16; k++) {
            float4 a0 = *(const float4*)&As[k][ty * 8];
            float4 a1 = *(const float4*)&As[k][ty * 8 + 4];
            float a[8] = {a0.x, a0.y, a0.z, a0.w, a1.x, a1.y, a1.z, a1.w};
            float4 bv = *(const float4*)&Bs[k][tx * 4];
            float bb[4] = {bv.x, bv.y, bv.z, bv.w};
            #pragma unroll
            for (int r = 0; r < 8; r++)
                #pragma unroll
                for (int j = 0; j < 4; j++) acc[r][j] = fmaf(a[r], bb[j], acc[r][j]);
        }
        __syncthreads();
    }

    // + b_dense, LN2 over 64 cols, relu, store
    #pragma unroll
    for (int r = 0; r < 8; r++)
        #pragma unroll
        for (int j = 0; j < 4; j++)
            buf[ty * 8 + r][tx * 4 + j] = acc[r][j] + bd[tx * 4 + j];
    __syncthreads();
    if (tid < 128) {
        float s = 0.f, q = 0.f;
        #pragma unroll
        for (int c = 0; c < 64; c++) { float v = buf[tid][c]; s += v; q += v * v; }
        float mu = s / 64.f;
        smu[tid] = mu;
        srs[tid] = rsqrtf(q / 64.f - mu * mu + 1e-12f);
    }
    __syncthreads();
    #pragma unroll
    for (int r = 0; r < 8; r++) {
        int lr = ty * 8 + r;
        float mu = smu[lr], rs = srs[lr];
        int gr = bx * 128 + lr;
        #pragma unroll
        for (int j = 0; j < 4; j++) {
            int c = tx * 4 + j;
            float y = (buf[lr][c] - mu) * rs * g2[c] + b2[c];
            g_x[(size_t)gr * DH_ + c] = fmaxf(y, 0.f);
        }
    }
}

// ---------------- K2: one LSTM step (both directions via blockIdx.z) ----------------
// GEMM: Z[2048, 2048] = [x_t | h_prev] @ W(576,2048), fused cell update.
// Block: BM=128 batch rows x (16 hidden units x 4 gates). Thread: 8 rows (4 f32x2 pairs) x 1 hidden unit x 4 gates.
__global__ void k2_step(const float* __restrict__ Wfw, const float* __restrict__ bfw,
                        const float* __restrict__ Wbw, const float* __restrict__ bbw,
                        const int* __restrict__ au, int t) {
    int dir = blockIdx.z;
    const float* W    = dir ? Wbw : Wfw;
    const float* bias = dir ? bbw : bfw;
    float* hs   = g_hs[dir];
    float* cbuf = g_c[dir];

    __shared__ float As[16][132];
    __shared__ u64   Bs[16][64];     // W values duplicated into both f32x2 lanes

    int tid = threadIdx.x;
    int bx = blockIdx.x;             // batch block (16 blocks of 128)
    int nb = blockIdx.y;             // hidden-unit block (32 blocks of 16)
    int ty = tid >> 4, tx = tid & 15;

    u64 acc[4][4];
    #pragma unroll
    for (int p = 0; p < 4; p++)
        #pragma unroll
        for (int g = 0; g < 4; g++) acc[p][g] = 0ull;

    #pragma unroll 1
    for (int kt = 0; kt < KIN; kt += 16) {
        // ---- A tile: [128 rows x 16 k] from x_t (k<64) or h_prev (k>=64) ----
        #pragma unroll
        for (int it = 0; it < 2; it++) {
            int v = tid + it * 256;
            int r = v >> 2, q = (v & 3) * 4;
            int gb = bx * 128 + r;
            float4 val;
            if (kt < 64) {
                int ts = t;
                if (dir) { int a = au[gb]; ts = (t < a) ? (a - 1 - t) : t; }
                val = *(const float4*)(g_x + (size_t)(gb * TT + ts) * DH_ + kt + q);
            } else if (t == 0) {
                val = make_float4(0.f, 0.f, 0.f, 0.f);
            } else {
                val = *(const float4*)(hs + (size_t)(t - 1) * (BB * HH) + (size_t)gb * HH + (kt - 64) + q);
            }
            As[q + 0][r] = val.x; As[q + 1][r] = val.y; As[q + 2][r] = val.z; As[q + 3][r] = val.w;
        }
        // ---- B tile: 16 k x 64 cols (col = gate*16 + nn), duplicated into f32x2 ----
        {
            int k = tid >> 4, c0 = (tid & 15) * 4;
            int g = c0 >> 4, nn = c0 & 15;
            float4 w = *(const float4*)(W + (size_t)(kt + k) * G4 + g * HH + nb * 16 + nn);
            Bs[k][c0 + 0] = pk2(w.x, w.x);
            Bs[k][c0 + 1] = pk2(w.y, w.y);
            Bs[k][c0 + 2] = pk2(w.z, w.z);
            Bs[k][c0 + 3] = pk2(w.w, w.w);
        }
        __syncthreads();
        #pragma unroll
        for (int k = 0; k < 16; k++) {
            const u64* ar = (const u64*)&As[k][ty * 8];   // 4 pairs of consecutive rows
            u64 ap0 = ar[0], ap1 = ar[1], ap2 = ar[2], ap3 = ar[3];
            u64 bv0 = Bs[k][tx], bv1 = Bs[k][16 + tx], bv2 = Bs[k][32 + tx], bv3 = Bs[k][48 + tx];
            fma2(acc[0][0], ap0, bv0); fma2(acc[0][1], ap0, bv1); fma2(acc[0][2], ap0, bv2); fma2(acc[0][3], ap0, bv3);
            fma2(acc[1][0], ap1, bv0); fma2(acc[1][1], ap1, bv1); fma2(acc[1][2], ap1, bv2); fma2(acc[1][3], ap1, bv3);
            fma2(acc[2][0], ap2, bv0); fma2(acc[2][1], ap2, bv1); fma2(acc[2][2], ap2, bv2); fma2(acc[2][3], ap2, bv3);
            fma2(acc[3][0], ap3, bv0); fma2(acc[3][1], ap3, bv1); fma2(acc[3][2], ap3, bv2); fma2(acc[3][3], ap3, bv3);
        }
        __syncthreads();
    }

    // ---- fused LSTM cell (thread owns all 4 gates of hidden unit n for 8 batch rows) ----
    int n = nb * 16 + tx;
    float bi = bias[0 * HH + n], bj = bias[1 * HH + n], bf = bias[2 * HH + n], bo = bias[3 * HH + n];
    #pragma unroll
    for (int p = 0; p < 4; p++) {
        float2 zi = upk2(acc[p][0]);
        float2 zj = upk2(acc[p][1]);
        float2 zf = upk2(acc[p][2]);
        float2 zo = upk2(acc[p][3]);
        #pragma unroll
        for (int h2 = 0; h2 < 2; h2++) {
            int lr = ty * 8 + p * 2 + h2;
            int gb = bx * 128 + lr;
            float vi = (h2 ? zi.y : zi.x) + bi;
            float vj = (h2 ? zj.y : zj.x) + bj;
            float vf = (h2 ? zf.y : zf.x) + bf;
            float vo = (h2 ? zo.y : zo.x) + bo;
            float cprev = (t == 0) ? 0.f : cbuf[(size_t)gb * HH + n];
            float cn = cprev * sigf(vf + 1.0f) + sigf(vi) * tanhf(vj);
            float hn = tanhf(cn) * sigf(vo);
            cbuf[(size_t)gb * HH + n] = cn;
            hs[(size_t)t * (BB * HH) + (size_t)gb * HH + n] = hn;   // unmasked (recurrence)
            int a = au[gb];
            bool m = (t < a);
            if (dir == 0) {
                g_hcat[(size_t)(gb * TT + t) * (2 * HH) + n] = m ? hn : 0.f;
            } else {
                int dst = m ? (a - 1 - t) : t;   // reverse_sequence scatter (involution)
                g_hcat[(size_t)(gb * TT + dst) * (2 * HH) + HH + n] = m ? hn : 0.f;
            }
        }
    }
}

// ---------------- K3: per-batch LN3 stats over (T, 2H) = 32768 values ----------------
__global__ void k3_stats() {
    __shared__ float ssum[256], ssq[256];
    int b = blockIdx.x, tid = threadIdx.x;
    const float4* p = (const float4*)(g_hcat + (size_t)b * (TT * 2 * HH));
    float s = 0.f, q = 0.f;
    for (int i = tid; i < (TT * 2 * HH) / 4; i += 256) {
        float4 v = p[i];
        s += v.x + v.y + v.z + v.w;
        q += v.x * v.x + v.y * v.y + v.z * v.z + v.w * v.w;
    }
    ssum[tid] = s; ssq[tid] = q;
    __syncthreads();
    for (int o = 128; o; o >>= 1) {
        if (tid < o) { ssum[tid] += ssum[tid + o]; ssq[tid] += ssq[tid + o]; }
        __syncthreads();
    }
    if (tid == 0) {
        float mu = ssum[0] / 32768.f;
        g_mu3[b] = mu;
        g_rs3[b] = rsqrtf(ssq[0] / 32768.f - mu * mu + 1e-12f);
    }
}

// ---------------- K4: relu(LN3) -> conv (1024x64 matmul) -> tanh ----------------
__global__ void k4_out(const float* __restrict__ g3, const float* __restrict__ b3,
                       const float* __restrict__ Wc, const float* __restrict__ bc,
                       float* __restrict__ out) {
    __shared__ float As[16][132];
    __shared__ float Bs[16][64];

    int tid = threadIdx.x;
    int bx = blockIdx.x;
    int ty = tid >> 4, tx = tid & 15;

    float acc[8][4];
    #pragma unroll
    for (int r = 0; r < 8; r++)
        #pragma unroll
        for (int j = 0; j < 4; j++) acc[r][j] = 0.f;

    #pragma unroll 1
    for (int kt = 0; kt < 2 * HH; kt += 16) {
        #pragma unroll
        for (int it = 0; it < 2; it++) {
            int v = tid + it * 256;
            int r = v >> 2, q = (v & 3) * 4;
            int gr = bx * 128 + r;
            int bat = gr >> 5;                      // row = b*T + t
            float4 val = *(const float4*)(g_hcat + (size_t)gr * (2 * HH) + kt + q);
            float mu = g_mu3[bat], rs = g_rs3[bat];
            As[q + 0][r] = fmaxf((val.x - mu) * rs * g3[kt + q + 0] + b3[kt + q + 0], 0.f);
            As[q + 1][r] = fmaxf((val.y - mu) * rs * g3[kt + q + 1] + b3[kt + q + 1], 0.f);
            As[q + 2][r] = fmaxf((val.z - mu) * rs * g3[kt + q + 2] + b3[kt + q + 2], 0.f);
            As[q + 3][r] = fmaxf((val.w - mu) * rs * g3[kt + q + 3] + b3[kt + q + 3], 0.f);
        }
        {
            int k = tid >> 4, c0 = (tid & 15) * 4;
            float4 w = *(const float4*)(Wc + (size_t)(kt + k) * AA + c0);
            Bs[k][c0 + 0] = w.x; Bs[k][c0 + 1] = w.y; Bs[k][c0 + 2] = w.z; Bs[k][c0 + 3] = w.w;
        }
        __syncthreads();
        #pragma unroll
        for (int k = 0; k < 16; k++) {
            float4 a0 = *(const float4*)&As[k][ty * 8];
            float4 a1 = *(const float4*)&As[k][ty * 8 + 4];
            float a[8] = {a0.x, a0.y, a0.z, a0.w, a1.x, a1.y, a1.z, a1.w};
            float4 bv = *(const float4*)&Bs[k][tx * 4];
            float bb[4] = {bv.x, bv.y, bv.z, bv.w};
            #pragma unroll
            for (int r = 0; r < 8; r++)
                #pragma unroll
                for (int j = 0; j < 4; j++) acc[r][j] = fmaf(a[r], bb[j], acc[r][j]);
        }
        __syncthreads();
    }

    #pragma unroll
    for (int r = 0; r < 8; r++) {
        int gr = bx * 128 + ty * 8 + r;
        #pragma unroll
        for (int j = 0; j < 4; j++) {
            int c = tx * 4 + j;
            out[(size_t)gr * AA + c] = tanhf(acc[r][j] + bc[c]);
        }
    }
}

// ---------------- launch ----------------
extern "C" void kernel_launch(void* const* d_in, const int* in_sizes, int n_in,
                              void* d_out, int out_size) {
    // Inputs: ud, mask(unused), au, [n_hidden scalar maybe], ln1_g, ln1_b, W_dense, b_dense,
    //         ln2_g, ln2_b, W_fw, b_fw, W_bw, b_bw, ln3_g, ln3_b, W_conv, b_conv
    int s = (n_in >= 18) ? 1 : 0;   // whether n_hidden scalar occupies slot 3
    const float* ud  = (const float*)d_in[0];
    const int*   au  = (const int*)  d_in[2];
    const float* g1  = (const float*)d_in[3 + s];
    const float* b1  = (const float*)d_in[4 + s];
    const float* Wd  = (const float*)d_in[5 + s];
    const float* bd  = (const float*)d_in[6 + s];
    const float* g2  = (const float*)d_in[7 + s];
    const float* b2  = (const float*)d_in[8 + s];
    const float* Wfw = (const float*)d_in[9 + s];
    const float* bfw = (const float*)d_in[10 + s];
    const float* Wbw = (const float*)d_in[11 + s];
    const float* bbw = (const float*)d_in[12 + s];
    const float* g3  = (const float*)d_in[13 + s];
    const float* b3  = (const float*)d_in[14 + s];
    const float* Wc  = (const float*)d_in[15 + s];
    const float* bc  = (const float*)d_in[16 + s];
    float* out = (float*)d_out;

    k0_rowstats<<<BT / 8, dim3(32, 8)>>>(ud);
    k1_dense<<<BT / 128, 256>>>(ud, g1, b1, Wd, bd, g2, b2);
    for (int t = 0; t < TT; t++)
        k2_step<<<dim3(BB / 128, HH / 16, 2), 256>>>(Wfw, bfw, Wbw, bbw, au, t);
    k3_stats<<<BB, 256>>>();
    k4_out<<<BT / 128, 256>>>(g3, b3, Wc, bc, out);
}

// round 3
// speedup vs baseline: 1.6925x; 1.6925x over previous
#include <cuda_runtime.h>
#include <cuda_bf16.h>
#include <math.h>
#include <stdint.h>

// Problem constants
#define BB   2048
#define TT   32
#define BT   65536        // BB*TT
#define DIN_ 1024
#define DH_  64
#define HH   512
#define G4   2048         // 4*H
#define KIN  576          // DH + H
#define AA   64

typedef unsigned long long u64;

#define SMEM_SWIZZLE_128B(off) ((off) ^ (((off) >> 3) & 0x70))

// ======================= portable mma/ldmatrix/cp.async helpers =======================
__device__ __forceinline__ uint32_t smem_to_u32(const void* p) {
    uint32_t a;
    asm("{ .reg .u64 t; cvta.to.shared.u64 t, %1; cvt.u32.u64 %0, t; }" : "=r"(a) : "l"(p));
    return a;
}
__device__ __forceinline__ void cpa16(uint32_t s, const void* g) {
    asm volatile("cp.async.cg.shared.global [%0], [%1], 16;" :: "r"(s), "l"(g));
}
__device__ __forceinline__ void ldsm4(uint32_t* r, uint32_t addr) {
    asm volatile("ldmatrix.sync.aligned.m8n8.x4.shared.b16 {%0,%1,%2,%3}, [%4];"
        : "=r"(r[0]), "=r"(r[1]), "=r"(r[2]), "=r"(r[3]) : "r"(addr));
}
__device__ __forceinline__ void mma16816(float* c, const uint32_t* a, const uint32_t* b) {
    asm volatile("mma.sync.aligned.m16n8k16.row.col.f32.bf16.bf16.f32 "
        "{%0,%1,%2,%3}, {%4,%5,%6,%7}, {%8,%9}, {%0,%1,%2,%3};"
        : "+f"(c[0]), "+f"(c[1]), "+f"(c[2]), "+f"(c[3])
        : "r"(a[0]), "r"(a[1]), "r"(a[2]), "r"(a[3]), "r"(b[0]), "r"(b[1]));
}

// ======================= scratch (device globals) =======================
__device__ float g_mu1[BT];
__device__ float g_rs1[BT];
__device__ __nv_bfloat16 g_xp[2][BT * DH_];          // [pass(hi/lo)][(b*T+t)*64+d]
__device__ __nv_bfloat16 g_wp[2][2][8][256 * 576];   // [dir][pass][nb][n'(256) * 576 + k], n'=nl*4+gate
__device__ __nv_bfloat16 g_hp[2][2][2][BB * HH];     // [dir][pass][buf(t&1)][b*512+n]
__device__ float g_c[2][BB * HH];                    // cell state
__device__ float g_hcat[BB * TT * 2 * HH];           // masked concat [b][t][1024]
__device__ float g_mu3[BB];
__device__ float g_rs3[BB];

__device__ __forceinline__ float sigf(float x) { return 1.0f / (1.0f + expf(-x)); }

// ---------------- K0: per-row mean / rstd of ud (LN1 stats) ----------------
__global__ void k0_rowstats(const float* __restrict__ ud) {
    int row = blockIdx.x * 8 + threadIdx.y;      // blockDim = (32, 8)
    const float4* p = (const float4*)(ud + (size_t)row * DIN_);
    float s = 0.f, q = 0.f;
    for (int i = threadIdx.x; i < DIN_ / 4; i += 32) {
        float4 v = p[i];
        s += v.x + v.y + v.z + v.w;
        q += v.x * v.x + v.y * v.y + v.z * v.z + v.w * v.w;
    }
    #pragma unroll
    for (int o = 16; o; o >>= 1) {
        s += __shfl_down_sync(0xffffffffu, s, o);
        q += __shfl_down_sync(0xffffffffu, q, o);
    }
    if (threadIdx.x == 0) {
        float mu = s / (float)DIN_;
        float var = q / (float)DIN_ - mu * mu;
        g_mu1[row] = mu;
        g_rs1[row] = rsqrtf(var + 1e-12f);
    }
}

// ---------------- KP: prepack W (both dirs) into bf16 hi/lo, gate-interleaved, K-major ----------------
__global__ void kp_w(const float* __restrict__ Wfw, const float* __restrict__ Wbw) {
    int idx = blockIdx.x * 256 + threadIdx.x;    // 2 * 576 * 2048 total
    int dir = idx >= (KIN * G4);
    int r = idx - dir * (KIN * G4);
    int k = r >> 11;
    int col = r & 2047;
    const float* W = dir ? Wbw : Wfw;
    float v = W[(size_t)k * G4 + col];
    __nv_bfloat16 hi = __float2bfloat16(v);
    __nv_bfloat16 lo = __float2bfloat16(v - __bfloat162float(hi));
    int g = col >> 9, rr = col & 511, nb = rr >> 6, nl = rr & 63;
    int np = nl * 4 + g;
    g_wp[dir][0][nb][np * 576 + k] = hi;
    g_wp[dir][1][nb][np * 576 + k] = lo;
}

// ---------------- K1: LN1 -> dense -> LN2 -> relu -> bf16 hi/lo pack ----------------
__global__ void k1_dense(const float* __restrict__ ud,
                         const float* __restrict__ g1, const float* __restrict__ b1,
                         const float* __restrict__ Wd, const float* __restrict__ bd,
                         const float* __restrict__ g2, const float* __restrict__ b2) {
    __shared__ float As[16][132];
    __shared__ float Bs[16][64];
    __shared__ float buf[128][65];
    __shared__ float smu[128], srs[128];

    int tid = threadIdx.x;
    int bx = blockIdx.x;
    int ty = tid >> 4, tx = tid & 15;

    float acc[8][4];
    #pragma unroll
    for (int r = 0; r < 8; r++)
        #pragma unroll
        for (int j = 0; j < 4; j++) acc[r][j] = 0.f;

    #pragma unroll 1
    for (int kt = 0; kt < DIN_; kt += 16) {
        #pragma unroll
        for (int it = 0; it < 2; it++) {
            int v = tid + it * 256;
            int r = v >> 2, q = (v & 3) * 4;
            int gr = bx * 128 + r;
            float4 val = *(const float4*)(ud + (size_t)gr * DIN_ + kt + q);
            float mu = g_mu1[gr], rs = g_rs1[gr];
            As[q + 0][r] = (val.x - mu) * rs * g1[kt + q + 0] + b1[kt + q + 0];
            As[q + 1][r] = (val.y - mu) * rs * g1[kt + q + 1] + b1[kt + q + 1];
            As[q + 2][r] = (val.z - mu) * rs * g1[kt + q + 2] + b1[kt + q + 2];
            As[q + 3][r] = (val.w - mu) * rs * g1[kt + q + 3] + b1[kt + q + 3];
        }
        {
            int k = tid >> 4, c0 = (tid & 15) * 4;
            float4 w = *(const float4*)(Wd + (size_t)(kt + k) * 64 + c0);
            Bs[k][c0 + 0] = w.x; Bs[k][c0 + 1] = w.y; Bs[k][c0 + 2] = w.z; Bs[k][c0 + 3] = w.w;
        }
        __syncthreads();
        #pragma unroll
        for (int k = 0; k < 16; k++) {
            float4 a0 = *(const float4*)&As[k][ty * 8];
            float4 a1 = *(const float4*)&As[k][ty * 8 + 4];
            float a[8] = {a0.x, a0.y, a0.z, a0.w, a1.x, a1.y, a1.z, a1.w};
            float4 bv = *(const float4*)&Bs[k][tx * 4];
            float bb[4] = {bv.x, bv.y, bv.z, bv.w};
            #pragma unroll
            for (int r = 0; r < 8; r++)
                #pragma unroll
                for (int j = 0; j < 4; j++) acc[r][j] = fmaf(a[r], bb[j], acc[r][j]);
        }
        __syncthreads();
    }

    #pragma unroll
    for (int r = 0; r < 8; r++)
        #pragma unroll
        for (int j = 0; j < 4; j++)
            buf[ty * 8 + r][tx * 4 + j] = acc[r][j] + bd[tx * 4 + j];
    __syncthreads();
    if (tid < 128) {
        float s = 0.f, q = 0.f;
        #pragma unroll
        for (int c = 0; c < 64; c++) { float v = buf[tid][c]; s += v; q += v * v; }
        float mu = s / 64.f;
        smu[tid] = mu;
        srs[tid] = rsqrtf(q / 64.f - mu * mu + 1e-12f);
    }
    __syncthreads();
    #pragma unroll
    for (int r = 0; r < 8; r++) {
        int lr = ty * 8 + r;
        float mu = smu[lr], rs = srs[lr];
        int gr = bx * 128 + lr;
        #pragma unroll
        for (int j = 0; j < 4; j++) {
            int c = tx * 4 + j;
            float y = (buf[lr][c] - mu) * rs * g2[c] + b2[c];
            y = fmaxf(y, 0.f);
            __nv_bfloat16 hi = __float2bfloat16(y);
            __nv_bfloat16 lo = __float2bfloat16(y - __bfloat162float(hi));
            g_xp[0][(size_t)gr * DH_ + c] = hi;
            g_xp[1][(size_t)gr * DH_ + c] = lo;
        }
    }
}

// ---------------- K2M: one LSTM step via mma.sync (3xBF16 split precision) ----------------
// grid (16 Mblk, 8 Nblk, 2 dir), 512 threads (16 warps), CTA tile M=128 x N=256
// (N = 64 units x 4 gates interleaved). Warp tile 32x64. K=576 in 9 chunks of 64,
// double-buffered SMEM (2 x 96KB) with cp.async prefetch.
__global__ void __launch_bounds__(512, 1)
k2m_step(const float* __restrict__ bfw, const float* __restrict__ bbw,
         const int* __restrict__ au, int t) {
    extern __shared__ __align__(16) char dsm[];

    int tid = threadIdx.x;
    int wid = tid >> 5, lid = tid & 31;
    int bx = blockIdx.x, nb = blockIdx.y, dir = blockIdx.z;
    int wm = wid & 3, wn = wid >> 2;           // warp grid 4x4 (M x N)

    uint32_t b32 = smem_to_u32(dsm);
    uint32_t pad = ((b32 + 1023) & ~1023u) - b32;
    char* tb = dsm + pad;
    uint32_t tb32 = b32 + pad;

    const __nv_bfloat16* whi = g_wp[dir][0][nb];
    const __nv_bfloat16* wlo = g_wp[dir][1][nb];
    int rb = (t & 1) ^ 1;
    const __nv_bfloat16* hhi = g_hp[dir][0][rb];
    const __nv_bfloat16* hlo = g_hp[dir][1][rb];

    int NC = (t == 0) ? 1 : 9;

    // ---- issue loads for chunk kc into stage s ----
    auto issue = [&](int kc, int s) {
        uint32_t sb = tb32 + s * 98304;
        #pragma unroll
        for (int i = 0; i < 2; i++) {                  // A hi+lo: 1024 x 16B each
            int idx = tid + i * 512;
            int row = idx >> 3, q = idx & 7;
            int gb = bx * 128 + row;
            const __nv_bfloat16 *srcH, *srcL;
            if (kc == 0) {
                int ts = t;
                if (dir) { int a0 = au[gb]; ts = (t < a0) ? (a0 - 1 - t) : t; }
                size_t el = ((size_t)gb * TT + ts) * DH_;
                srcH = g_xp[0] + el; srcL = g_xp[1] + el;
            } else {
                size_t el = (size_t)gb * HH + (kc - 1) * 64;
                srcH = hhi + el; srcL = hlo + el;
            }
            uint32_t sw = SMEM_SWIZZLE_128B(row * 128 + q * 16);
            cpa16(sb + sw,         (const char*)srcH + q * 16);
            cpa16(sb + 16384 + sw, (const char*)srcL + q * 16);
        }
        #pragma unroll
        for (int i = 0; i < 4; i++) {                  // B hi+lo: 2048 x 16B each
            int idx = tid + i * 512;
            int row = idx >> 3, q = idx & 7;
            size_t el = (size_t)row * KIN + kc * 64;
            uint32_t sw = SMEM_SWIZZLE_128B(row * 128 + q * 16);
            cpa16(sb + 32768 + sw, (const char*)(whi + el) + q * 16);
            cpa16(sb + 65536 + sw, (const char*)(wlo + el) + q * 16);
        }
        asm volatile("cp.async.commit_group;" ::: "memory");
    };

    float acc[2][8][4];
    #pragma unroll
    for (int mt = 0; mt < 2; mt++)
        #pragma unroll
        for (int nt = 0; nt < 8; nt++)
            #pragma unroll
            for (int j = 0; j < 4; j++) acc[mt][nt][j] = 0.f;

    // ldmatrix lane address components
    int lar = (lid & 7) + ((lid >> 3) & 1) * 8;    // A: row-in-16
    int lac = ((lid >> 4) & 1) * 8;                // A: col-in-16
    int lbr = (lid & 7) + ((lid >> 4) & 1) * 8;    // B: row-in-16
    int lbc = ((lid >> 3) & 1) * 8;                // B: col-in-16

    issue(0, 0);
    #pragma unroll 1
    for (int kc = 0; kc < NC; kc++) {
        if (kc + 1 < NC) {
            issue(kc + 1, (kc + 1) & 1);
            asm volatile("cp.async.wait_group 1;" ::: "memory");
        } else {
            asm volatile("cp.async.wait_group 0;" ::: "memory");
        }
        __syncthreads();

        uint32_t sb = tb32 + (kc & 1) * 98304;
        uint32_t aH = sb, aL = sb + 16384, bH = sb + 32768, bL = sb + 65536;

        #pragma unroll
        for (int kt = 0; kt < 4; kt++) {
            uint32_t ahi[2][4], alo[2][4], bhi[4][4], blo[4][4];
            #pragma unroll
            for (int mt = 0; mt < 2; mt++) {
                uint32_t off = SMEM_SWIZZLE_128B((uint32_t)((wm * 32 + mt * 16 + lar) * 128 + (kt * 16 + lac) * 2));
                ldsm4(ahi[mt], aH + off);
                ldsm4(alo[mt], aL + off);
            }
            #pragma unroll
            for (int np = 0; np < 4; np++) {
                uint32_t off = SMEM_SWIZZLE_128B((uint32_t)((wn * 64 + np * 16 + lbr) * 128 + (kt * 16 + lbc) * 2));
                ldsm4(bhi[np], bH + off);
                ldsm4(blo[np], bL + off);
            }
            #pragma unroll
            for (int mt = 0; mt < 2; mt++)
                #pragma unroll
                for (int nt = 0; nt < 8; nt++)
                    mma16816(acc[mt][nt], ahi[mt], &bhi[nt >> 1][(nt & 1) * 2]);
            #pragma unroll
            for (int mt = 0; mt < 2; mt++)
                #pragma unroll
                for (int nt = 0; nt < 8; nt++)
                    mma16816(acc[mt][nt], ahi[mt], &blo[nt >> 1][(nt & 1) * 2]);
            #pragma unroll
            for (int mt = 0; mt < 2; mt++)
                #pragma unroll
                for (int nt = 0; nt < 8; nt++)
                    mma16816(acc[mt][nt], alo[mt], &bhi[nt >> 1][(nt & 1) * 2]);
        }
        __syncthreads();
    }

    // ---- stage C to smem: [128][264] floats ----
    float* Cs = (float*)tb;
    #pragma unroll
    for (int mt = 0; mt < 2; mt++) {
        int row = wm * 32 + mt * 16 + (lid >> 2);
        #pragma unroll
        for (int nt = 0; nt < 8; nt++) {
            int col = wn * 64 + nt * 8 + 2 * (lid & 3);
            Cs[row * 264 + col]       = acc[mt][nt][0];
            Cs[row * 264 + col + 1]   = acc[mt][nt][1];
            Cs[(row + 8) * 264 + col]     = acc[mt][nt][2];
            Cs[(row + 8) * 264 + col + 1] = acc[mt][nt][3];
        }
    }
    __syncthreads();

    // ---- LSTM cell update: 8192 cells / 512 threads = 16 each ----
    {
        const float* bias = dir ? bbw : bfw;
        int r = tid & 127;
        int u0 = (tid >> 7) * 16;
        int gb = bx * 128 + r;
        int a0 = au[gb];
        bool m = (t < a0);
        float* cptr = g_c[dir] + (size_t)gb * HH + nb * 64;
        __nv_bfloat16* ohh = g_hp[dir][0][t & 1] + (size_t)gb * HH + nb * 64;
        __nv_bfloat16* ohl = g_hp[dir][1][t & 1] + (size_t)gb * HH + nb * 64;
        size_t hc;
        if (dir == 0) hc = ((size_t)gb * TT + t) * (2 * HH) + nb * 64;
        else {
            int dst = m ? (a0 - 1 - t) : t;
            hc = ((size_t)gb * TT + dst) * (2 * HH) + HH + nb * 64;
        }
        #pragma unroll
        for (int uu = 0; uu < 16; uu++) {
            int u = u0 + uu;
            int n = nb * 64 + u;
            float4 z = *(float4*)&Cs[r * 264 + u * 4];
            float vi = z.x + bias[n];
            float vj = z.y + bias[HH + n];
            float vf = z.z + bias[2 * HH + n];
            float vo = z.w + bias[3 * HH + n];
            float cp = (t == 0) ? 0.f : cptr[u];
            float cn = cp * sigf(vf + 1.0f) + sigf(vi) * tanhf(vj);
            float hn = tanhf(cn) * sigf(vo);
            cptr[u] = cn;
            __nv_bfloat16 hi = __float2bfloat16(hn);
            ohh[u] = hi;
            ohl[u] = __float2bfloat16(hn - __bfloat162float(hi));
            g_hcat[hc + u] = m ? hn : 0.f;
        }
    }
}

// ---------------- K3: per-batch LN3 stats over (T, 2H) ----------------
__global__ void k3_stats() {
    __shared__ float ssum[256], ssq[256];
    int b = blockIdx.x, tid = threadIdx.x;
    const float4* p = (const float4*)(g_hcat + (size_t)b * (TT * 2 * HH));
    float s = 0.f, q = 0.f;
    for (int i = tid; i < (TT * 2 * HH) / 4; i += 256) {
        float4 v = p[i];
        s += v.x + v.y + v.z + v.w;
        q += v.x * v.x + v.y * v.y + v.z * v.z + v.w * v.w;
    }
    ssum[tid] = s; ssq[tid] = q;
    __syncthreads();
    for (int o = 128; o; o >>= 1) {
        if (tid < o) { ssum[tid] += ssum[tid + o]; ssq[tid] += ssq[tid + o]; }
        __syncthreads();
    }
    if (tid == 0) {
        float mu = ssum[0] / 32768.f;
        g_mu3[b] = mu;
        g_rs3[b] = rsqrtf(ssq[0] / 32768.f - mu * mu + 1e-12f);
    }
}

// ---------------- K4: relu(LN3) -> conv matmul -> tanh ----------------
__global__ void k4_out(const float* __restrict__ g3, const float* __restrict__ b3,
                       const float* __restrict__ Wc, const float* __restrict__ bc,
                       float* __restrict__ out) {
    __shared__ float As[16][132];
    __shared__ float Bs[16][64];

    int tid = threadIdx.x;
    int bx = blockIdx.x;
    int ty = tid >> 4, tx = tid & 15;

    float acc[8][4];
    #pragma unroll
    for (int r = 0; r < 8; r++)
        #pragma unroll
        for (int j = 0; j < 4; j++) acc[r][j] = 0.f;

    #pragma unroll 1
    for (int kt = 0; kt < 2 * HH; kt += 16) {
        #pragma unroll
        for (int it = 0; it < 2; it++) {
            int v = tid + it * 256;
            int r = v >> 2, q = (v & 3) * 4;
            int gr = bx * 128 + r;
            int bat = gr >> 5;
            float4 val = *(const float4*)(g_hcat + (size_t)gr * (2 * HH) + kt + q);
            float mu = g_mu3[bat], rs = g_rs3[bat];
            As[q + 0][r] = fmaxf((val.x - mu) * rs * g3[kt + q + 0] + b3[kt + q + 0], 0.f);
            As[q + 1][r] = fmaxf((val.y - mu) * rs * g3[kt + q + 1] + b3[kt + q + 1], 0.f);
            As[q + 2][r] = fmaxf((val.z - mu) * rs * g3[kt + q + 2] + b3[kt + q + 2], 0.f);
            As[q + 3][r] = fmaxf((val.w - mu) * rs * g3[kt + q + 3] + b3[kt + q + 3], 0.f);
        }
        {
            int k = tid >> 4, c0 = (tid & 15) * 4;
            float4 w = *(const float4*)(Wc + (size_t)(kt + k) * AA + c0);
            Bs[k][c0 + 0] = w.x; Bs[k][c0 + 1] = w.y; Bs[k][c0 + 2] = w.z; Bs[k][c0 + 3] = w.w;
        }
        __syncthreads();
        #pragma unroll
        for (int k = 0; k < 16; k++) {
            float4 a0 = *(const float4*)&As[k][ty * 8];
            float4 a1 = *(const float4*)&As[k][ty * 8 + 4];
            float a[8] = {a0.x, a0.y, a0.z, a0.w, a1.x, a1.y, a1.z, a1.w};
            float4 bv = *(const float4*)&Bs[k][tx * 4];
            float bb[4] = {bv.x, bv.y, bv.z, bv.w};
            #pragma unroll
            for (int r = 0; r < 8; r++)
                #pragma unroll
                for (int j = 0; j < 4; j++) acc[r][j] = fmaf(a[r], bb[j], acc[r][j]);
        }
        __syncthreads();
    }

    #pragma unroll
    for (int r = 0; r < 8; r++) {
        int gr = bx * 128 + ty * 8 + r;
        #pragma unroll
        for (int j = 0; j < 4; j++) {
            int c = tx * 4 + j;
            out[(size_t)gr * AA + c] = tanhf(acc[r][j] + bc[c]);
        }
    }
}

// ---------------- launch ----------------
extern "C" void kernel_launch(void* const* d_in, const int* in_sizes, int n_in,
                              void* d_out, int out_size) {
    int s = (n_in >= 18) ? 1 : 0;
    const float* ud  = (const float*)d_in[0];
    const int*   au  = (const int*)  d_in[2];
    const float* g1  = (const float*)d_in[3 + s];
    const float* b1  = (const float*)d_in[4 + s];
    const float* Wd  = (const float*)d_in[5 + s];
    const float* bd  = (const float*)d_in[6 + s];
    const float* g2  = (const float*)d_in[7 + s];
    const float* b2  = (const float*)d_in[8 + s];
    const float* Wfw = (const float*)d_in[9 + s];
    const float* bfw = (const float*)d_in[10 + s];
    const float* Wbw = (const float*)d_in[11 + s];
    const float* bbw = (const float*)d_in[12 + s];
    const float* g3  = (const float*)d_in[13 + s];
    const float* b3  = (const float*)d_in[14 + s];
    const float* Wc  = (const float*)d_in[15 + s];
    const float* bc  = (const float*)d_in[16 + s];
    float* out = (float*)d_out;

    const int K2_SMEM = 2 * 98304 + 1024;   // 197632 bytes dynamic
    static int attr_set = 0;
    if (!attr_set) {
        cudaFuncSetAttribute(k2m_step, cudaFuncAttributeMaxDynamicSharedMemorySize, K2_SMEM);
        attr_set = 1;
    }

    kp_w<<<(2 * KIN * G4) / 256, 256>>>(Wfw, Wbw);
    k0_rowstats<<<BT / 8, dim3(32, 8)>>>(ud);
    k1_dense<<<BT / 128, 256>>>(ud, g1, b1, Wd, bd, g2, b2);
    for (int t = 0; t < TT; t++)
        k2m_step<<<dim3(BB / 128, HH / 64, 2), 512, K2_SMEM>>>(bfw, bbw, au, t);
    k3_stats<<<BB, 256>>>();
    k4_out<<<BT / 128, 256>>>(g3, b3, Wc, bc, out);
}

// round 4
// speedup vs baseline: 1.9849x; 1.1728x over previous
#include <cuda_runtime.h>
#include <cuda_bf16.h>
#include <math.h>
#include <stdint.h>

// Problem constants
#define BB   2048
#define TT   32
#define BT   65536        // BB*TT
#define DIN_ 1024
#define DH_  64
#define HH   512
#define G4   2048         // 4*H
#define KIN  576          // DH + H
#define AA   64

typedef unsigned long long u64;

#define SMEM_SWIZZLE_128B(off) ((off) ^ (((off) >> 3) & 0x70))

// ======================= mma/ldmatrix/cp.async helpers =======================
__device__ __forceinline__ uint32_t smem_to_u32(const void* p) {
    uint32_t a;
    asm("{ .reg .u64 t; cvta.to.shared.u64 t, %1; cvt.u32.u64 %0, t; }" : "=r"(a) : "l"(p));
    return a;
}
__device__ __forceinline__ void cpa16(uint32_t s, const void* g) {
    asm volatile("cp.async.cg.shared.global [%0], [%1], 16;" :: "r"(s), "l"(g));
}
__device__ __forceinline__ void ldsm4(uint32_t* r, uint32_t addr) {
    asm volatile("ldmatrix.sync.aligned.m8n8.x4.shared.b16 {%0,%1,%2,%3}, [%4];"
        : "=r"(r[0]), "=r"(r[1]), "=r"(r[2]), "=r"(r[3]) : "r"(addr));
}
__device__ __forceinline__ void mma16816(float* c, const uint32_t* a, const uint32_t* b) {
    asm volatile("mma.sync.aligned.m16n8k16.row.col.f32.bf16.bf16.f32 "
        "{%0,%1,%2,%3}, {%4,%5,%6,%7}, {%8,%9}, {%0,%1,%2,%3};"
        : "+f"(c[0]), "+f"(c[1]), "+f"(c[2]), "+f"(c[3])
        : "r"(a[0]), "r"(a[1]), "r"(a[2]), "r"(a[3]), "r"(b[0]), "r"(b[1]));
}

// ======================= scratch (device globals) =======================
__device__ float g_mu1[BT];
__device__ float g_rs1[BT];
__device__ __nv_bfloat16 g_xp[2][BT * DH_];          // [pass(hi/lo)][(b*T+t)*64+d]
__device__ __nv_bfloat16 g_wp[2][2][8][256 * 576];   // [dir][pass][nb][n'(256)*576 + k], n'=nl*4+gate
__device__ __nv_bfloat16 g_hp[2][2][2][BB * HH];     // [dir][pass][buf(t&1)][b*512+n]
__device__ float g_c[2][BB * HH];                    // cell state
__device__ float g_hcat[BB * TT * 2 * HH];           // masked concat [b][t][1024]
__device__ float g_mu3[BB];
__device__ float g_rs3[BB];
__device__ unsigned g_bar[32];                       // group barriers (dir*16+Mblk), zero-init

__device__ __forceinline__ float sigf(float x) { return 1.0f / (1.0f + expf(-x)); }

// ---------------- K0: per-row mean / rstd of ud (LN1 stats) ----------------
__global__ void k0_rowstats(const float* __restrict__ ud) {
    int row = blockIdx.x * 8 + threadIdx.y;      // blockDim = (32, 8)
    const float4* p = (const float4*)(ud + (size_t)row * DIN_);
    float s = 0.f, q = 0.f;
    for (int i = threadIdx.x; i < DIN_ / 4; i += 32) {
        float4 v = p[i];
        s += v.x + v.y + v.z + v.w;
        q += v.x * v.x + v.y * v.y + v.z * v.z + v.w * v.w;
    }
    #pragma unroll
    for (int o = 16; o; o >>= 1) {
        s += __shfl_down_sync(0xffffffffu, s, o);
        q += __shfl_down_sync(0xffffffffu, q, o);
    }
    if (threadIdx.x == 0) {
        float mu = s / (float)DIN_;
        float var = q / (float)DIN_ - mu * mu;
        g_mu1[row] = mu;
        g_rs1[row] = rsqrtf(var + 1e-12f);
    }
}

// ---------------- KP: prepack W into bf16 hi/lo, gate-interleaved, K-major ----------------
__global__ void kp_w(const float* __restrict__ Wfw, const float* __restrict__ Wbw) {
    int idx = blockIdx.x * 256 + threadIdx.x;    // 2 * 576 * 2048 total
    int dir = idx >= (KIN * G4);
    int r = idx - dir * (KIN * G4);
    int k = r >> 11;
    int col = r & 2047;
    const float* W = dir ? Wbw : Wfw;
    float v = W[(size_t)k * G4 + col];
    __nv_bfloat16 hi = __float2bfloat16(v);
    __nv_bfloat16 lo = __float2bfloat16(v - __bfloat162float(hi));
    int g = col >> 9, rr = col & 511, nb = rr >> 6, nl = rr & 63;
    int np = nl * 4 + g;
    g_wp[dir][0][nb][np * 576 + k] = hi;
    g_wp[dir][1][nb][np * 576 + k] = lo;
}

// ---------------- K1: LN1 -> dense -> LN2 -> relu -> bf16 hi/lo pack ----------------
__global__ void k1_dense(const float* __restrict__ ud,
                         const float* __restrict__ g1, const float* __restrict__ b1,
                         const float* __restrict__ Wd, const float* __restrict__ bd,
                         const float* __restrict__ g2, const float* __restrict__ b2) {
    __shared__ float As[16][132];
    __shared__ float Bs[16][64];
    __shared__ float buf[128][65];
    __shared__ float smu[128], srs[128];

    int tid = threadIdx.x;
    int bx = blockIdx.x;
    int ty = tid >> 4, tx = tid & 15;

    float acc[8][4];
    #pragma unroll
    for (int r = 0; r < 8; r++)
        #pragma unroll
        for (int j = 0; j < 4; j++) acc[r][j] = 0.f;

    #pragma unroll 1
    for (int kt = 0; kt < DIN_; kt += 16) {
        #pragma unroll
        for (int it = 0; it < 2; it++) {
            int v = tid + it * 256;
            int r = v >> 2, q = (v & 3) * 4;
            int gr = bx * 128 + r;
            float4 val = *(const float4*)(ud + (size_t)gr * DIN_ + kt + q);
            float mu = g_mu1[gr], rs = g_rs1[gr];
            As[q + 0][r] = (val.x - mu) * rs * g1[kt + q + 0] + b1[kt + q + 0];
            As[q + 1][r] = (val.y - mu) * rs * g1[kt + q + 1] + b1[kt + q + 1];
            As[q + 2][r] = (val.z - mu) * rs * g1[kt + q + 2] + b1[kt + q + 2];
            As[q + 3][r] = (val.w - mu) * rs * g1[kt + q + 3] + b1[kt + q + 3];
        }
        {
            int k = tid >> 4, c0 = (tid & 15) * 4;
            float4 w = *(const float4*)(Wd + (size_t)(kt + k) * 64 + c0);
            Bs[k][c0 + 0] = w.x; Bs[k][c0 + 1] = w.y; Bs[k][c0 + 2] = w.z; Bs[k][c0 + 3] = w.w;
        }
        __syncthreads();
        #pragma unroll
        for (int k = 0; k < 16; k++) {
            float4 a0 = *(const float4*)&As[k][ty * 8];
            float4 a1 = *(const float4*)&As[k][ty * 8 + 4];
            float a[8] = {a0.x, a0.y, a0.z, a0.w, a1.x, a1.y, a1.z, a1.w};
            float4 bv = *(const float4*)&Bs[k][tx * 4];
            float bb[4] = {bv.x, bv.y, bv.z, bv.w};
            #pragma unroll
            for (int r = 0; r < 8; r++)
                #pragma unroll
                for (int j = 0; j < 4; j++) acc[r][j] = fmaf(a[r], bb[j], acc[r][j]);
        }
        __syncthreads();
    }

    #pragma unroll
    for (int r = 0; r < 8; r++)
        #pragma unroll
        for (int j = 0; j < 4; j++)
            buf[ty * 8 + r][tx * 4 + j] = acc[r][j] + bd[tx * 4 + j];
    __syncthreads();
    if (tid < 128) {
        float s = 0.f, q = 0.f;
        #pragma unroll
        for (int c = 0; c < 64; c++) { float v = buf[tid][c]; s += v; q += v * v; }
        float mu = s / 64.f;
        smu[tid] = mu;
        srs[tid] = rsqrtf(q / 64.f - mu * mu + 1e-12f);
    }
    __syncthreads();
    #pragma unroll
    for (int r = 0; r < 8; r++) {
        int lr = ty * 8 + r;
        float mu = smu[lr], rs = srs[lr];
        int gr = bx * 128 + lr;
        #pragma unroll
        for (int j = 0; j < 4; j++) {
            int c = tx * 4 + j;
            float y = (buf[lr][c] - mu) * rs * g2[c] + b2[c];
            y = fmaxf(y, 0.f);
            __nv_bfloat16 hi = __float2bfloat16(y);
            __nv_bfloat16 lo = __float2bfloat16(y - __bfloat162float(hi));
            g_xp[0][(size_t)gr * DH_ + c] = hi;
            g_xp[1][(size_t)gr * DH_ + c] = lo;
        }
    }
}

// ---------------- K2P: persistent bidirectional LSTM, all 32 steps ----------------
// grid (16 Mblk, 4 nbPair, 2 dir) = 128 CTAs (all resident), 512 threads (16 warps).
// Per step per CTA: 2 N-blocks of 256 gate-cols (64 units x 4 gates interleaved),
// CTA tile M=128 x N=256, warp tile 32x64, K=576 in 9 chunks of 64,
// double-buffered smem (2 x 96KB) cp.async pipeline, register epilogue via shfl,
// 4-CTA group barrier between steps.
__global__ void __launch_bounds__(512, 1)
k2p_persist(const float* __restrict__ bfw, const float* __restrict__ bbw,
            const int* __restrict__ au) {
    extern __shared__ __align__(16) char dsm[];

    int tid = threadIdx.x;
    int wid = tid >> 5, lid = tid & 31;
    int bx = blockIdx.x, npair = blockIdx.y, dir = blockIdx.z;
    int wm = wid & 3, wn = wid >> 2;           // warp grid 4x4 (M x N)
    int grp = dir * 16 + bx;

    uint32_t b32 = smem_to_u32(dsm);
    uint32_t pad = ((b32 + 1023) & ~1023u) - b32;
    uint32_t tb32 = b32 + pad;

    const float* bias = dir ? bbw : bfw;

    // ---- thread-invariant cp.async smem offsets ----
    uint32_t swA[2], swB[4];
    int gbA[2], qA8[2];                    // A source row / 16B-group
    int boff[4];                           // B source element offsets (w/o kc)
    #pragma unroll
    for (int i = 0; i < 2; i++) {
        int idx = tid + i * 512;
        int row = idx >> 3, q = idx & 7;
        swA[i] = SMEM_SWIZZLE_128B((uint32_t)(row * 128 + q * 16));
        gbA[i] = bx * 128 + row;
        qA8[i] = q * 8;
    }
    #pragma unroll
    for (int i = 0; i < 4; i++) {
        int idx = tid + i * 512;
        int row = idx >> 3, q = idx & 7;
        swB[i] = SMEM_SWIZZLE_128B((uint32_t)(row * 128 + q * 16));
        boff[i] = row * KIN + q * 8;
    }

    // ---- ldmatrix thread-invariant components ----
    int lar = (lid & 7) + ((lid >> 3) & 1) * 8;
    int lac2 = (((lid >> 4) & 1) * 8) * 2;
    int lbr = (lid & 7) + ((lid >> 4) & 1) * 8;
    int lbc2 = (((lid >> 3) & 1) * 8) * 2;
    uint32_t aBase[2], aMask[2], bBase[4], bMask[4];
    #pragma unroll
    for (int mt = 0; mt < 2; mt++) {
        int r = wm * 32 + mt * 16 + lar;
        aBase[mt] = (uint32_t)(r * 128);
        aMask[mt] = (uint32_t)((r & 7) << 4);
    }
    #pragma unroll
    for (int np = 0; np < 4; np++) {
        int r = wn * 64 + np * 16 + lbr;
        bBase[np] = (uint32_t)(r * 128);
        bMask[np] = (uint32_t)((r & 7) << 4);
    }

    // ---- epilogue thread-invariant components ----
    int l2 = lid & 3;
    int erow[2];                 // cell rows (mt)
    int ea[2];                   // au per row
    #pragma unroll
    for (int mt = 0; mt < 2; mt++) {
        erow[mt] = wm * 32 + mt * 16 + (lid >> 2) + (l2 & 1) * 8;
        ea[mt] = au[bx * 128 + erow[mt]];
    }

    float acc[2][8][4];
    #pragma unroll
    for (int mt = 0; mt < 2; mt++)
        #pragma unroll
        for (int nt = 0; nt < 8; nt++)
            #pragma unroll
            for (int j = 0; j < 4; j++) acc[mt][nt][j] = 0.f;

    #pragma unroll 1
    for (int t = 0; t < TT; t++) {
        int rb = (t & 1) ^ 1;
        const __nv_bfloat16* hH = g_hp[dir][0][rb];
        const __nv_bfloat16* hL = g_hp[dir][1][rb];

        // per-step x source offsets (kc==0)
        int xoff[2];
        #pragma unroll
        for (int i = 0; i < 2; i++) {
            int ts = t;
            if (dir) { int a0 = ea[0]; a0 = au[gbA[i]]; ts = (t < a0) ? (a0 - 1 - t) : t; }
            xoff[i] = (gbA[i] * TT + ts) * DH_ + qA8[i];
        }

        int NC = (t == 0) ? 1 : 9;
        int total = 2 * NC;

        auto issue = [&](int ci) {
            int half = (ci >= NC) ? 1 : 0;
            int kc = ci - half * NC;
            uint32_t sb = tb32 + (uint32_t)(ci & 1) * 98304u;
            if (kc == 0) {
                #pragma unroll
                for (int i = 0; i < 2; i++) {
                    cpa16(sb + swA[i],         g_xp[0] + xoff[i]);
                    cpa16(sb + 16384 + swA[i], g_xp[1] + xoff[i]);
                }
            } else {
                int e0 = (kc - 1) * 64;
                #pragma unroll
                for (int i = 0; i < 2; i++) {
                    int e = gbA[i] * HH + e0 + qA8[i];
                    cpa16(sb + swA[i],         hH + e);
                    cpa16(sb + 16384 + swA[i], hL + e);
                }
            }
            int nb = npair * 2 + half;
            const __nv_bfloat16* wH = g_wp[dir][0][nb];
            const __nv_bfloat16* wL = g_wp[dir][1][nb];
            int ke = kc * 64;
            #pragma unroll
            for (int i = 0; i < 4; i++) {
                int e = boff[i] + ke;
                cpa16(sb + 32768 + swB[i], wH + e);
                cpa16(sb + 65536 + swB[i], wL + e);
            }
            asm volatile("cp.async.commit_group;" ::: "memory");
        };

        issue(0);
        #pragma unroll 1
        for (int ci = 0; ci < total; ci++) {
            if (ci + 1 < total) {
                issue(ci + 1);
                asm volatile("cp.async.wait_group 1;" ::: "memory");
            } else {
                asm volatile("cp.async.wait_group 0;" ::: "memory");
            }
            __syncthreads();

            uint32_t sb = tb32 + (uint32_t)(ci & 1) * 98304u;
            #pragma unroll
            for (int kt = 0; kt < 4; kt++) {
                uint32_t ahi[2][4], alo[2][4], bhi[4][4], blo[4][4];
                #pragma unroll
                for (int mt = 0; mt < 2; mt++) {
                    uint32_t off = sb + aBase[mt] + (((uint32_t)(kt * 32 + lac2)) ^ aMask[mt]);
                    ldsm4(ahi[mt], off);
                    ldsm4(alo[mt], off + 16384);
                }
                #pragma unroll
                for (int np = 0; np < 4; np++) {
                    uint32_t off = sb + 32768 + bBase[np] + (((uint32_t)(kt * 32 + lbc2)) ^ bMask[np]);
                    ldsm4(bhi[np], off);
                    ldsm4(blo[np], off + 32768);
                }
                #pragma unroll
                for (int mt = 0; mt < 2; mt++)
                    #pragma unroll
                    for (int nt = 0; nt < 8; nt++)
                        mma16816(acc[mt][nt], ahi[mt], &bhi[nt >> 1][(nt & 1) * 2]);
                #pragma unroll
                for (int mt = 0; mt < 2; mt++)
                    #pragma unroll
                    for (int nt = 0; nt < 8; nt++)
                        mma16816(acc[mt][nt], ahi[mt], &blo[nt >> 1][(nt & 1) * 2]);
                #pragma unroll
                for (int mt = 0; mt < 2; mt++)
                    #pragma unroll
                    for (int nt = 0; nt < 8; nt++)
                        mma16816(acc[mt][nt], alo[mt], &bhi[nt >> 1][(nt & 1) * 2]);
            }
            __syncthreads();

            // ---- end of half: register epilogue (LSTM cell) ----
            int half = (ci >= NC) ? 1 : 0;
            int kc = ci - half * NC;
            if (kc == NC - 1) {
                int nb = npair * 2 + half;
                bool oddl = (l2 & 1);
                __nv_bfloat16* ohh = g_hp[dir][0][t & 1];
                __nv_bfloat16* ohl = g_hp[dir][1][t & 1];
                #pragma unroll
                for (int mt = 0; mt < 2; mt++) {
                    int row = erow[mt];
                    int gb = bx * 128 + row;
                    int a0 = ea[mt];
                    bool m = (t < a0);
                    float* cptr = g_c[dir] + (size_t)gb * HH + nb * 64;
                    size_t hb = (size_t)gb * HH + nb * 64;
                    size_t hc;
                    if (dir == 0) hc = ((size_t)gb * TT + t) * (2 * HH) + nb * 64;
                    else {
                        int dst = m ? (a0 - 1 - t) : t;
                        hc = ((size_t)gb * TT + dst) * (2 * HH) + HH + nb * 64;
                    }
                    #pragma unroll
                    for (int nt = 0; nt < 8; nt++) {
                        float o0 = acc[mt][nt][0], o1 = acc[mt][nt][1];
                        float o2 = acc[mt][nt][2], o3 = acc[mt][nt][3];
                        float r0 = __shfl_xor_sync(0xffffffffu, o0, 1);
                        float r1 = __shfl_xor_sync(0xffffffffu, o1, 1);
                        float r2 = __shfl_xor_sync(0xffffffffu, o2, 1);
                        float r3 = __shfl_xor_sync(0xffffffffu, o3, 1);
                        float zi, zj, zf, zo;
                        if (!oddl) { zi = o0; zj = o1; zf = r0; zo = r1; }
                        else       { zi = r2; zj = r3; zf = o2; zo = o3; }
                        int u = wn * 16 + nt * 2 + (l2 >> 1);
                        int n = nb * 64 + u;
                        float vi = zi + bias[n];
                        float vj = zj + bias[HH + n];
                        float vf = zf + bias[2 * HH + n];
                        float vo = zo + bias[3 * HH + n];
                        float cp = (t == 0) ? 0.f : cptr[u];
                        float cn = cp * sigf(vf + 1.0f) + sigf(vi) * tanhf(vj);
                        float hn = tanhf(cn) * sigf(vo);
                        cptr[u] = cn;
                        __nv_bfloat16 hi = __float2bfloat16(hn);
                        ohh[hb + u] = hi;
                        ohl[hb + u] = __float2bfloat16(hn - __bfloat162float(hi));
                        g_hcat[hc + u] = m ? hn : 0.f;
                    }
                }
                // reset acc for next half/step
                #pragma unroll
                for (int mt = 0; mt < 2; mt++)
                    #pragma unroll
                    for (int nt = 0; nt < 8; nt++)
                        #pragma unroll
                        for (int j = 0; j < 4; j++) acc[mt][nt][j] = 0.f;
            }
        }

        // ---- inter-step group barrier (4 CTAs sharing (dir, Mblk)) ----
        if (t < TT - 1) {
            __syncthreads();
            if (tid == 0) {
                __threadfence();
                atomicAdd(&g_bar[grp], 1u);
                unsigned target = 4u * (unsigned)(t + 1);
                while (atomicAdd(&g_bar[grp], 0u) < target) __nanosleep(64);
            }
            __syncthreads();
        }
    }

    // final arrival + reset for graph-replay determinism
    __syncthreads();
    if (tid == 0) {
        __threadfence();
        atomicAdd(&g_bar[grp], 1u);
        if (npair == 0) {
            while (atomicAdd(&g_bar[grp], 0u) < 4u * (unsigned)TT) __nanosleep(64);
            g_bar[grp] = 0u;
            __threadfence();
        }
    }
}

// ---------------- K3: per-batch LN3 stats over (T, 2H) ----------------
__global__ void k3_stats() {
    __shared__ float ssum[256], ssq[256];
    int b = blockIdx.x, tid = threadIdx.x;
    const float4* p = (const float4*)(g_hcat + (size_t)b * (TT * 2 * HH));
    float s = 0.f, q = 0.f;
    for (int i = tid; i < (TT * 2 * HH) / 4; i += 256) {
        float4 v = p[i];
        s += v.x + v.y + v.z + v.w;
        q += v.x * v.x + v.y * v.y + v.z * v.z + v.w * v.w;
    }
    ssum[tid] = s; ssq[tid] = q;
    __syncthreads();
    for (int o = 128; o; o >>= 1) {
        if (tid < o) { ssum[tid] += ssum[tid + o]; ssq[tid] += ssq[tid + o]; }
        __syncthreads();
    }
    if (tid == 0) {
        float mu = ssum[0] / 32768.f;
        g_mu3[b] = mu;
        g_rs3[b] = rsqrtf(ssq[0] / 32768.f - mu * mu + 1e-12f);
    }
}

// ---------------- K4: relu(LN3) -> conv matmul -> tanh ----------------
__global__ void k4_out(const float* __restrict__ g3, const float* __restrict__ b3,
                       const float* __restrict__ Wc, const float* __restrict__ bc,
                       float* __restrict__ out) {
    __shared__ float As[16][132];
    __shared__ float Bs[16][64];

    int tid = threadIdx.x;
    int bx = blockIdx.x;
    int ty = tid >> 4, tx = tid & 15;

    float acc[8][4];
    #pragma unroll
    for (int r = 0; r < 8; r++)
        #pragma unroll
        for (int j = 0; j < 4; j++) acc[r][j] = 0.f;

    #pragma unroll 1
    for (int kt = 0; kt < 2 * HH; kt += 16) {
        #pragma unroll
        for (int it = 0; it < 2; it++) {
            int v = tid + it * 256;
            int r = v >> 2, q = (v & 3) * 4;
            int gr = bx * 128 + r;
            int bat = gr >> 5;
            float4 val = *(const float4*)(g_hcat + (size_t)gr * (2 * HH) + kt + q);
            float mu = g_mu3[bat], rs = g_rs3[bat];
            As[q + 0][r] = fmaxf((val.x - mu) * rs * g3[kt + q + 0] + b3[kt + q + 0], 0.f);
            As[q + 1][r] = fmaxf((val.y - mu) * rs * g3[kt + q + 1] + b3[kt + q + 1], 0.f);
            As[q + 2][r] = fmaxf((val.z - mu) * rs * g3[kt + q + 2] + b3[kt + q + 2], 0.f);
            As[q + 3][r] = fmaxf((val.w - mu) * rs * g3[kt + q + 3] + b3[kt + q + 3], 0.f);
        }
        {
            int k = tid >> 4, c0 = (tid & 15) * 4;
            float4 w = *(const float4*)(Wc + (size_t)(kt + k) * AA + c0);
            Bs[k][c0 + 0] = w.x; Bs[k][c0 + 1] = w.y; Bs[k][c0 + 2] = w.z; Bs[k][c0 + 3] = w.w;
        }
        __syncthreads();
        #pragma unroll
        for (int k = 0; k < 16; k++) {
            float4 a0 = *(const float4*)&As[k][ty * 8];
            float4 a1 = *(const float4*)&As[k][ty * 8 + 4];
            float a[8] = {a0.x, a0.y, a0.z, a0.w, a1.x, a1.y, a1.z, a1.w};
            float4 bv = *(const float4*)&Bs[k][tx * 4];
            float bb[4] = {bv.x, bv.y, bv.z, bv.w};
            #pragma unroll
            for (int r = 0; r < 8; r++)
                #pragma unroll
                for (int j = 0; j < 4; j++) acc[r][j] = fmaf(a[r], bb[j], acc[r][j]);
        }
        __syncthreads();
    }

    #pragma unroll
    for (int r = 0; r < 8; r++) {
        int gr = bx * 128 + ty * 8 + r;
        #pragma unroll
        for (int j = 0; j < 4; j++) {
            int c = tx * 4 + j;
            out[(size_t)gr * AA + c] = tanhf(acc[r][j] + bc[c]);
        }
    }
}

// ---------------- launch ----------------
extern "C" void kernel_launch(void* const* d_in, const int* in_sizes, int n_in,
                              void* d_out, int out_size) {
    int s = (n_in >= 18) ? 1 : 0;
    const float* ud  = (const float*)d_in[0];
    const int*   au  = (const int*)  d_in[2];
    const float* g1  = (const float*)d_in[3 + s];
    const float* b1  = (const float*)d_in[4 + s];
    const float* Wd  = (const float*)d_in[5 + s];
    const float* bd  = (const float*)d_in[6 + s];
    const float* g2  = (const float*)d_in[7 + s];
    const float* b2  = (const float*)d_in[8 + s];
    const float* Wfw = (const float*)d_in[9 + s];
    const float* bfw = (const float*)d_in[10 + s];
    const float* Wbw = (const float*)d_in[11 + s];
    const float* bbw = (const float*)d_in[12 + s];
    const float* g3  = (const float*)d_in[13 + s];
    const float* b3  = (const float*)d_in[14 + s];
    const float* Wc  = (const float*)d_in[15 + s];
    const float* bc  = (const float*)d_in[16 + s];
    float* out = (float*)d_out;

    const int K2_SMEM = 2 * 98304 + 1024;   // 197632 bytes dynamic
    cudaFuncSetAttribute(k2p_persist, cudaFuncAttributeMaxDynamicSharedMemorySize, K2_SMEM);

    kp_w<<<(2 * KIN * G4) / 256, 256>>>(Wfw, Wbw);
    k0_rowstats<<<BT / 8, dim3(32, 8)>>>(ud);
    k1_dense<<<BT / 128, 256>>>(ud, g1, b1, Wd, bd, g2, b2);
    k2p_persist<<<dim3(16, 4, 2), 512, K2_SMEM>>>(bfw, bbw, au);
    k3_stats<<<BB, 256>>>();
    k4_out<<<BT / 128, 256>>>(g3, b3, Wc, bc, out);
}

// round 5
// speedup vs baseline: 2.3883x; 1.2032x over previous
#include <cuda_runtime.h>
#include <cuda_fp16.h>
#include <math.h>
#include <stdint.h>

// Problem constants
#define BB   2048
#define TT   32
#define BT   65536        // BB*TT
#define DIN_ 1024
#define DH_  64
#define HH   512
#define G4   2048         // 4*H
#define KIN  576          // DH + H
#define AA   64

typedef unsigned long long u64;

#define SW64(off) ((off) ^ (((off) >> 3) & 0x30))

// ======================= helpers =======================
__device__ __forceinline__ uint32_t smem_to_u32(const void* p) {
    uint32_t a;
    asm("{ .reg .u64 t; cvta.to.shared.u64 t, %1; cvt.u32.u64 %0, t; }" : "=r"(a) : "l"(p));
    return a;
}
__device__ __forceinline__ void cpa16(uint32_t s, const void* g) {
    asm volatile("cp.async.cg.shared.global [%0], [%1], 16;" :: "r"(s), "l"(g));
}
#define CP_COMMIT() asm volatile("cp.async.commit_group;" ::: "memory")
#define CP_WAIT(n)  asm volatile("cp.async.wait_group %0;" :: "n"(n) : "memory")
__device__ __forceinline__ void ldsm4(uint32_t* r, uint32_t addr) {
    asm volatile("ldmatrix.sync.aligned.m8n8.x4.shared.b16 {%0,%1,%2,%3}, [%4];"
        : "=r"(r[0]), "=r"(r[1]), "=r"(r[2]), "=r"(r[3]) : "r"(addr));
}
__device__ __forceinline__ void mma16816h(float* c, const uint32_t* a, const uint32_t* b) {
    asm volatile("mma.sync.aligned.m16n8k16.row.col.f32.f16.f16.f32 "
        "{%0,%1,%2,%3}, {%4,%5,%6,%7}, {%8,%9}, {%0,%1,%2,%3};"
        : "+f"(c[0]), "+f"(c[1]), "+f"(c[2]), "+f"(c[3])
        : "r"(a[0]), "r"(a[1]), "r"(a[2]), "r"(a[3]), "r"(b[0]), "r"(b[1]));
}
__device__ __forceinline__ u64 pk2(float lo, float hi) {
    u64 r; asm("mov.b64 %0, {%1, %2};" : "=l"(r) : "f"(lo), "f"(hi)); return r;
}
__device__ __forceinline__ float2 upk2(u64 v) {
    float2 f; asm("mov.b64 {%0, %1}, %2;" : "=f"(f.x), "=f"(f.y) : "l"(v)); return f;
}
__device__ __forceinline__ void fma2(u64 &d, u64 a, u64 b) {
    asm("fma.rn.f32x2 %0, %1, %2, %0;" : "+l"(d) : "l"(a), "l"(b));
}
__device__ __forceinline__ float sigf(float x) { return 1.0f / (1.0f + expf(-x)); }

// ======================= scratch (device globals) =======================
__device__ float g_mu1[BT];
__device__ float g_rs1[BT];
__device__ __half g_xph[BT * DH_];              // x hi plane
__device__ __half g_xpl[BT * DH_];              // x lo plane
__device__ __half g_wph[2][8][256 * 576];       // [dir][nb][n'(256)*576 + k], n'=nl*4+gate (fp16, single plane)
__device__ __half g_hhi[2][2][BB * HH];         // [dir][buf][b*512+n]
__device__ __half g_hlo[2][2][BB * HH];
__device__ float g_c[2][BB * HH];               // cell state
__device__ float g_hcat[BB * TT * 2 * HH];      // masked concat [b][t][1024]
__device__ float g_mu3[BB];
__device__ float g_rs3[BB];
__device__ unsigned g_bar[32];                  // group barriers (dir*16+Mblk), zero-init

// ---------------- K0: per-row mean / rstd of ud (LN1 stats) ----------------
__global__ void k0_rowstats(const float* __restrict__ ud) {
    int row = blockIdx.x * 8 + threadIdx.y;      // blockDim = (32, 8)
    const float4* p = (const float4*)(ud + (size_t)row * DIN_);
    float s = 0.f, q = 0.f;
    for (int i = threadIdx.x; i < DIN_ / 4; i += 32) {
        float4 v = p[i];
        s += v.x + v.y + v.z + v.w;
        q += v.x * v.x + v.y * v.y + v.z * v.z + v.w * v.w;
    }
    #pragma unroll
    for (int o = 16; o; o >>= 1) {
        s += __shfl_down_sync(0xffffffffu, s, o);
        q += __shfl_down_sync(0xffffffffu, q, o);
    }
    if (threadIdx.x == 0) {
        float mu = s / (float)DIN_;
        float var = q / (float)DIN_ - mu * mu;
        g_mu1[row] = mu;
        g_rs1[row] = rsqrtf(var + 1e-12f);
    }
}

// ---------------- KP: prepack W into fp16, gate-interleaved, K-major ----------------
__global__ void kp_w(const float* __restrict__ Wfw, const float* __restrict__ Wbw) {
    int idx = blockIdx.x * 256 + threadIdx.x;    // 2 * 576 * 2048 total
    int dir = idx >= (KIN * G4);
    int r = idx - dir * (KIN * G4);
    int k = r >> 11;
    int col = r & 2047;
    const float* W = dir ? Wbw : Wfw;
    float v = W[(size_t)k * G4 + col];
    int g = col >> 9, rr = col & 511, nb = rr >> 6, nl = rr & 63;
    int np = nl * 4 + g;
    g_wph[dir][nb][np * 576 + k] = __float2half(v);
}

// ---------------- K1: LN1 -> dense -> LN2 -> relu -> fp16 hi/lo pack (f32x2 inner) ----------------
__global__ void k1_dense(const float* __restrict__ ud,
                         const float* __restrict__ g1, const float* __restrict__ b1,
                         const float* __restrict__ Wd, const float* __restrict__ bd,
                         const float* __restrict__ g2, const float* __restrict__ b2) {
    __shared__ float As[16][132];
    __shared__ float Bs[16][64];
    __shared__ float buf[128][65];
    __shared__ float smu[128], srs[128];

    int tid = threadIdx.x;
    int bx = blockIdx.x;
    int ty = tid >> 4, tx = tid & 15;

    u64 acc2[4][4];
    #pragma unroll
    for (int p = 0; p < 4; p++)
        #pragma unroll
        for (int j = 0; j < 4; j++) acc2[p][j] = 0ull;

    #pragma unroll 1
    for (int kt = 0; kt < DIN_; kt += 16) {
        #pragma unroll
        for (int it = 0; it < 2; it++) {
            int v = tid + it * 256;
            int r = v >> 2, q = (v & 3) * 4;
            int gr = bx * 128 + r;
            float4 val = *(const float4*)(ud + (size_t)gr * DIN_ + kt + q);
            float mu = g_mu1[gr], rs = g_rs1[gr];
            As[q + 0][r] = (val.x - mu) * rs * g1[kt + q + 0] + b1[kt + q + 0];
            As[q + 1][r] = (val.y - mu) * rs * g1[kt + q + 1] + b1[kt + q + 1];
            As[q + 2][r] = (val.z - mu) * rs * g1[kt + q + 2] + b1[kt + q + 2];
            As[q + 3][r] = (val.w - mu) * rs * g1[kt + q + 3] + b1[kt + q + 3];
        }
        {
            int k = tid >> 4, c0 = (tid & 15) * 4;
            float4 w = *(const float4*)(Wd + (size_t)(kt + k) * 64 + c0);
            Bs[k][c0 + 0] = w.x; Bs[k][c0 + 1] = w.y; Bs[k][c0 + 2] = w.z; Bs[k][c0 + 3] = w.w;
        }
        __syncthreads();
        #pragma unroll
        for (int k = 0; k < 16; k++) {
            const u64* ar = (const u64*)&As[k][ty * 8];
            float4 bv = *(const float4*)&Bs[k][tx * 4];
            u64 b0 = pk2(bv.x, bv.x), b1d = pk2(bv.y, bv.y);
            u64 b2d = pk2(bv.z, bv.z), b3 = pk2(bv.w, bv.w);
            #pragma unroll
            for (int p = 0; p < 4; p++) {
                u64 ap = ar[p];
                fma2(acc2[p][0], ap, b0);
                fma2(acc2[p][1], ap, b1d);
                fma2(acc2[p][2], ap, b2d);
                fma2(acc2[p][3], ap, b3);
            }
        }
        __syncthreads();
    }

    #pragma unroll
    for (int p = 0; p < 4; p++)
        #pragma unroll
        for (int j = 0; j < 4; j++) {
            float2 v = upk2(acc2[p][j]);
            float bb = bd[tx * 4 + j];
            buf[ty * 8 + p * 2 + 0][tx * 4 + j] = v.x + bb;
            buf[ty * 8 + p * 2 + 1][tx * 4 + j] = v.y + bb;
        }
    __syncthreads();
    if (tid < 128) {
        float s = 0.f, q = 0.f;
        #pragma unroll
        for (int c = 0; c < 64; c++) { float v = buf[tid][c]; s += v; q += v * v; }
        float mu = s / 64.f;
        smu[tid] = mu;
        srs[tid] = rsqrtf(q / 64.f - mu * mu + 1e-12f);
    }
    __syncthreads();
    #pragma unroll
    for (int r = 0; r < 8; r++) {
        int lr = ty * 8 + r;
        float mu = smu[lr], rs = srs[lr];
        int gr = bx * 128 + lr;
        #pragma unroll
        for (int j = 0; j < 4; j++) {
            int c = tx * 4 + j;
            float y = (buf[lr][c] - mu) * rs * g2[c] + b2[c];
            y = fmaxf(y, 0.f);
            __half hi = __float2half(y);
            __half lo = __float2half(y - __half2float(hi));
            g_xph[(size_t)gr * DH_ + c] = hi;
            g_xpl[(size_t)gr * DH_ + c] = lo;
        }
    }
}

// ---------------- K2P: persistent bidirectional LSTM (fp16 2-pass, deep pipeline) ----------------
// grid (16 Mblk, 4 nbPair, 2 dir) = 128 CTAs, 512 threads (16 warps).
// CTA tile M=128 x N=256 per half (2 halves/step). K=576 in 18 chunks of 32.
// 6 smem stages x 32KB (A hi 8K + A lo 8K + B 16K), prefetch window 4,
// one syncthreads per chunk, cross-step x-prefetch, 4-CTA group barrier.
__global__ void __launch_bounds__(512, 1)
k2p_persist(const float* __restrict__ bfw, const float* __restrict__ bbw,
            const int* __restrict__ au) {
    extern __shared__ __align__(16) char dsm[];

    int tid = threadIdx.x;
    int wid = tid >> 5, lid = tid & 31;
    int bx = blockIdx.x, npair = blockIdx.y, dir = blockIdx.z;
    int wm = wid & 3, wn = wid >> 2;           // warp grid 4x4 (M x N)
    int grp = dir * 16 + bx;

    uint32_t b32 = smem_to_u32(dsm);
    uint32_t tb32 = (b32 + 1023) & ~1023u;

    const float* bias = dir ? bbw : bfw;

    // ---- cp.async invariants: A planes (1 unit/thread/plane), B (2 units/thread) ----
    uint32_t swA; int gbA, qA8, aA;
    {
        int row = tid >> 2, q = tid & 3;
        swA = SW64((uint32_t)(row * 64 + q * 16));
        gbA = bx * 128 + row;
        qA8 = q * 8;
        aA = au[gbA];
    }
    uint32_t swB[2]; int boff[2];
    #pragma unroll
    for (int i = 0; i < 2; i++) {
        int idx = tid + i * 512;
        int row = idx >> 2, q = idx & 3;
        swB[i] = SW64((uint32_t)(row * 64 + q * 16));
        boff[i] = row * KIN + q * 8;
    }

    // ---- ldmatrix invariants ----
    int lar = (lid & 7) + ((lid >> 3) & 1) * 8;
    int lac2 = (((lid >> 4) & 1) * 8) * 2;
    int lbr = (lid & 7) + ((lid >> 4) & 1) * 8;
    int lbc2 = (((lid >> 3) & 1) * 8) * 2;
    uint32_t aBase[2], aXor[2], bBase[4], bXor[4];
    #pragma unroll
    for (int mt = 0; mt < 2; mt++) {
        int r = wm * 32 + mt * 16 + lar;
        aBase[mt] = (uint32_t)(r * 64);
        aXor[mt] = (uint32_t)((r & 6) << 3);
    }
    #pragma unroll
    for (int np = 0; np < 4; np++) {
        int r = wn * 64 + np * 16 + lbr;
        bBase[np] = (uint32_t)(r * 64);
        bXor[np] = (uint32_t)((r & 6) << 3);
    }

    // ---- epilogue invariants ----
    int l2 = lid & 3;
    int erow[2], ea[2];
    #pragma unroll
    for (int mt = 0; mt < 2; mt++) {
        erow[mt] = wm * 32 + mt * 16 + (lid >> 2) + (l2 & 1) * 8;
        ea[mt] = au[bx * 128 + erow[mt]];
    }

    float acc[2][8][4];
    #pragma unroll
    for (int mt = 0; mt < 2; mt++)
        #pragma unroll
        for (int nt = 0; nt < 8; nt++)
            #pragma unroll
            for (int j = 0; j < 4; j++) acc[mt][nt][j] = 0.f;

    int sbuf = 0, cbuf = 0;

    // issue chunk ci of step t into stage sbuf
    auto issueC = [&](int t, int ci) {
        int NC = (t == 0) ? 2 : 18;
        int half = (ci >= NC) ? 1 : 0;
        int kc = ci - half * NC;
        uint32_t sb = tb32 + (uint32_t)sbuf * 32768u;
        if (kc < 2) {
            int ts = t;
            if (dir) ts = (t < aA) ? (aA - 1 - t) : t;
            int e = (gbA * TT + ts) * DH_ + kc * 32 + qA8;
            cpa16(sb + swA,        g_xph + e);
            cpa16(sb + 8192 + swA, g_xpl + e);
        } else {
            int bufsel = (t & 1) ^ 1;
            int e = gbA * HH + (kc - 2) * 32 + qA8;
            cpa16(sb + swA,        g_hhi[dir][bufsel] + e);
            cpa16(sb + 8192 + swA, g_hlo[dir][bufsel] + e);
        }
        int nb = npair * 2 + half;
        const __half* wp = g_wph[dir][nb];
        int ke = kc * 32;
        #pragma unroll
        for (int i = 0; i < 2; i++)
            cpa16(sb + 16384 + swB[i], wp + boff[i] + ke);
        CP_COMMIT();
        sbuf = (sbuf == 5) ? 0 : sbuf + 1;
    };

    // kernel start: issue first two chunks of t=0 (x chunks)
    issueC(0, 0);
    issueC(0, 1);

    #pragma unroll 1
    for (int t = 0; t < TT; t++) {
        int NC = (t == 0) ? 2 : 18;
        int NC2 = 2 * NC;

        // step top: fill prefetch window (chunks 2, 3)
        issueC(t, 2);
        issueC(t, 3);

        #pragma unroll 1
        for (int ci = 0; ci < NC2; ci++) {
            if (ci <= NC2 - 4)      CP_WAIT(3);
            else if (ci == NC2 - 3) CP_WAIT(2);
            else if (ci == NC2 - 2) CP_WAIT(1);
            else                    CP_WAIT(0);
            __syncthreads();
            if (ci + 4 < NC2) issueC(t, ci + 4);

            uint32_t sb = tb32 + (uint32_t)cbuf * 32768u;
            cbuf = (cbuf == 5) ? 0 : cbuf + 1;
            uint32_t aH = sb, aL = sb + 8192, bBm = sb + 16384;

            #pragma unroll
            for (int kt = 0; kt < 2; kt++) {
                uint32_t ahi[2][4], alo[2][4], bfr[4][4];
                #pragma unroll
                for (int mt = 0; mt < 2; mt++) {
                    uint32_t cb = ((uint32_t)(kt * 32 + lac2)) ^ aXor[mt];
                    ldsm4(ahi[mt], aH + aBase[mt] + cb);
                    ldsm4(alo[mt], aL + aBase[mt] + cb);
                }
                #pragma unroll
                for (int np = 0; np < 4; np++) {
                    uint32_t cb = ((uint32_t)(kt * 32 + lbc2)) ^ bXor[np];
                    ldsm4(bfr[np], bBm + bBase[np] + cb);
                }
                #pragma unroll
                for (int mt = 0; mt < 2; mt++)
                    #pragma unroll
                    for (int nt = 0; nt < 8; nt++)
                        mma16816h(acc[mt][nt], ahi[mt], &bfr[nt >> 1][(nt & 1) * 2]);
                #pragma unroll
                for (int mt = 0; mt < 2; mt++)
                    #pragma unroll
                    for (int nt = 0; nt < 8; nt++)
                        mma16816h(acc[mt][nt], alo[mt], &bfr[nt >> 1][(nt & 1) * 2]);
            }

            // ---- end of half: LSTM cell epilogue ----
            if (ci == NC - 1 || ci == NC2 - 1) {
                int half = (ci >= NC) ? 1 : 0;
                int nb = npair * 2 + half;
                bool oddl = (l2 & 1);
                __half* ohh = g_hhi[dir][t & 1];
                __half* ohl = g_hlo[dir][t & 1];
                #pragma unroll
                for (int mt = 0; mt < 2; mt++) {
                    int row = erow[mt];
                    int gb = bx * 128 + row;
                    int a0 = ea[mt];
                    bool m = (t < a0);
                    float* cptr = g_c[dir] + (size_t)gb * HH + nb * 64;
                    size_t hb = (size_t)gb * HH + nb * 64;
                    size_t hc;
                    if (dir == 0) hc = ((size_t)gb * TT + t) * (2 * HH) + nb * 64;
                    else {
                        int dst = m ? (a0 - 1 - t) : t;
                        hc = ((size_t)gb * TT + dst) * (2 * HH) + HH + nb * 64;
                    }
                    #pragma unroll
                    for (int nt = 0; nt < 8; nt++) {
                        float o0 = acc[mt][nt][0], o1 = acc[mt][nt][1];
                        float o2 = acc[mt][nt][2], o3 = acc[mt][nt][3];
                        float r0 = __shfl_xor_sync(0xffffffffu, o0, 1);
                        float r1 = __shfl_xor_sync(0xffffffffu, o1, 1);
                        float r2 = __shfl_xor_sync(0xffffffffu, o2, 1);
                        float r3 = __shfl_xor_sync(0xffffffffu, o3, 1);
                        float zi, zj, zf, zo;
                        if (!oddl) { zi = o0; zj = o1; zf = r0; zo = r1; }
                        else       { zi = r2; zj = r3; zf = o2; zo = o3; }
                        int u = wn * 16 + nt * 2 + (l2 >> 1);
                        int n = nb * 64 + u;
                        float vi = zi + bias[n];
                        float vj = zj + bias[HH + n];
                        float vf = zf + bias[2 * HH + n];
                        float vo = zo + bias[3 * HH + n];
                        float cp = (t == 0) ? 0.f : cptr[u];
                        float cn = cp * sigf(vf + 1.0f) + sigf(vi) * tanhf(vj);
                        float hn = tanhf(cn) * sigf(vo);
                        cptr[u] = cn;
                        __half hi = __float2half(hn);
                        ohh[hb + u] = hi;
                        ohl[hb + u] = __float2half(hn - __half2float(hi));
                        g_hcat[hc + u] = m ? hn : 0.f;
                    }
                }
                #pragma unroll
                for (int mt = 0; mt < 2; mt++)
                    #pragma unroll
                    for (int nt = 0; nt < 8; nt++)
                        #pragma unroll
                        for (int j = 0; j < 4; j++) acc[mt][nt][j] = 0.f;
            }
        }

        // ---- cross-step prefetch (x chunks of t+1; no barrier dependency) ----
        if (t < TT - 1) {
            issueC(t + 1, 0);
            issueC(t + 1, 1);
            // ---- inter-step group barrier (4 CTAs sharing (dir, Mblk)) ----
            __syncthreads();
            if (tid == 0) {
                __threadfence();
                atomicAdd(&g_bar[grp], 1u);
                unsigned target = 4u * (unsigned)(t + 1);
                while (atomicAdd(&g_bar[grp], 0u) < target) __nanosleep(64);
            }
            __syncthreads();
        }
    }

    // final arrival + reset for graph-replay determinism
    __syncthreads();
    if (tid == 0) {
        __threadfence();
        atomicAdd(&g_bar[grp], 1u);
        if (npair == 0) {
            while (atomicAdd(&g_bar[grp], 0u) < 4u * (unsigned)TT) __nanosleep(64);
            g_bar[grp] = 0u;
            __threadfence();
        }
    }
}

// ---------------- K3: per-batch LN3 stats over (T, 2H) ----------------
__global__ void k3_stats() {
    __shared__ float ssum[256], ssq[256];
    int b = blockIdx.x, tid = threadIdx.x;
    const float4* p = (const float4*)(g_hcat + (size_t)b * (TT * 2 * HH));
    float s = 0.f, q = 0.f;
    for (int i = tid; i < (TT * 2 * HH) / 4; i += 256) {
        float4 v = p[i];
        s += v.x + v.y + v.z + v.w;
        q += v.x * v.x + v.y * v.y + v.z * v.z + v.w * v.w;
    }
    ssum[tid] = s; ssq[tid] = q;
    __syncthreads();
    for (int o = 128; o; o >>= 1) {
        if (tid < o) { ssum[tid] += ssum[tid + o]; ssq[tid] += ssq[tid + o]; }
        __syncthreads();
    }
    if (tid == 0) {
        float mu = ssum[0] / 32768.f;
        g_mu3[b] = mu;
        g_rs3[b] = rsqrtf(ssq[0] / 32768.f - mu * mu + 1e-12f);
    }
}

// ---------------- K4: relu(LN3) -> conv matmul -> tanh (f32x2 inner) ----------------
__global__ void k4_out(const float* __restrict__ g3, const float* __restrict__ b3,
                       const float* __restrict__ Wc, const float* __restrict__ bc,
                       float* __restrict__ out) {
    __shared__ float As[16][132];
    __shared__ float Bs[16][64];

    int tid = threadIdx.x;
    int bx = blockIdx.x;
    int ty = tid >> 4, tx = tid & 15;

    u64 acc2[4][4];
    #pragma unroll
    for (int p = 0; p < 4; p++)
        #pragma unroll
        for (int j = 0; j < 4; j++) acc2[p][j] = 0ull;

    #pragma unroll 1
    for (int kt = 0; kt < 2 * HH; kt += 16) {
        #pragma unroll
        for (int it = 0; it < 2; it++) {
            int v = tid + it * 256;
            int r = v >> 2, q = (v & 3) * 4;
            int gr = bx * 128 + r;
            int bat = gr >> 5;
            float4 val = *(const float4*)(g_hcat + (size_t)gr * (2 * HH) + kt + q);
            float mu = g_mu3[bat], rs = g_rs3[bat];
            As[q + 0][r] = fmaxf((val.x - mu) * rs * g3[kt + q + 0] + b3[kt + q + 0], 0.f);
            As[q + 1][r] = fmaxf((val.y - mu) * rs * g3[kt + q + 1] + b3[kt + q + 1], 0.f);
            As[q + 2][r] = fmaxf((val.z - mu) * rs * g3[kt + q + 2] + b3[kt + q + 2], 0.f);
            As[q + 3][r] = fmaxf((val.w - mu) * rs * g3[kt + q + 3] + b3[kt + q + 3], 0.f);
        }
        {
            int k = tid >> 4, c0 = (tid & 15) * 4;
            float4 w = *(const float4*)(Wc + (size_t)(kt + k) * AA + c0);
            Bs[k][c0 + 0] = w.x; Bs[k][c0 + 1] = w.y; Bs[k][c0 + 2] = w.z; Bs[k][c0 + 3] = w.w;
        }
        __syncthreads();
        #pragma unroll
        for (int k = 0; k < 16; k++) {
            const u64* ar = (const u64*)&As[k][ty * 8];
            float4 bv = *(const float4*)&Bs[k][tx * 4];
            u64 b0 = pk2(bv.x, bv.x), b1d = pk2(bv.y, bv.y);
            u64 b2d = pk2(bv.z, bv.z), b3d = pk2(bv.w, bv.w);
            #pragma unroll
            for (int p = 0; p < 4; p++) {
                u64 ap = ar[p];
                fma2(acc2[p][0], ap, b0);
                fma2(acc2[p][1], ap, b1d);
                fma2(acc2[p][2], ap, b2d);
                fma2(acc2[p][3], ap, b3d);
            }
        }
        __syncthreads();
    }

    #pragma unroll
    for (int p = 0; p < 4; p++) {
        int gr0 = bx * 128 + ty * 8 + p * 2;
        #pragma unroll
        for (int j = 0; j < 4; j++) {
            float2 v = upk2(acc2[p][j]);
            int c = tx * 4 + j;
            out[(size_t)gr0 * AA + c]       = tanhf(v.x + bc[c]);
            out[(size_t)(gr0 + 1) * AA + c] = tanhf(v.y + bc[c]);
        }
    }
}

// ---------------- launch ----------------
extern "C" void kernel_launch(void* const* d_in, const int* in_sizes, int n_in,
                              void* d_out, int out_size) {
    int s = (n_in >= 18) ? 1 : 0;
    const float* ud  = (const float*)d_in[0];
    const int*   au  = (const int*)  d_in[2];
    const float* g1  = (const float*)d_in[3 + s];
    const float* b1  = (const float*)d_in[4 + s];
    const float* Wd  = (const float*)d_in[5 + s];
    const float* bd  = (const float*)d_in[6 + s];
    const float* g2  = (const float*)d_in[7 + s];
    const float* b2  = (const float*)d_in[8 + s];
    const float* Wfw = (const float*)d_in[9 + s];
    const float* bfw = (const float*)d_in[10 + s];
    const float* Wbw = (const float*)d_in[11 + s];
    const float* bbw = (const float*)d_in[12 + s];
    const float* g3  = (const float*)d_in[13 + s];
    const float* b3  = (const float*)d_in[14 + s];
    const float* Wc  = (const float*)d_in[15 + s];
    const float* bc  = (const float*)d_in[16 + s];
    float* out = (float*)d_out;

    const int K2_SMEM = 6 * 32768 + 1024;   // 197632 bytes dynamic
    cudaFuncSetAttribute(k2p_persist, cudaFuncAttributeMaxDynamicSharedMemorySize, K2_SMEM);

    kp_w<<<(2 * KIN * G4) / 256, 256>>>(Wfw, Wbw);
    k0_rowstats<<<BT / 8, dim3(32, 8)>>>(ud);
    k1_dense<<<BT / 128, 256>>>(ud, g1, b1, Wd, bd, g2, b2);
    k2p_persist<<<dim3(16, 4, 2), 512, K2_SMEM>>>(bfw, bbw, au);
    k3_stats<<<BB, 256>>>();
    k4_out<<<BT / 128, 256>>>(g3, b3, Wc, bc, out);
}

// round 6
// speedup vs baseline: 2.7712x; 1.1603x over previous
#include <cuda_runtime.h>
#include <cuda_fp16.h>
#include <math.h>
#include <stdint.h>

// Problem constants
#define BB   2048
#define TT   32
#define BT   65536        // BB*TT
#define DIN_ 1024
#define DH_  64
#define HH   512
#define G4   2048         // 4*H
#define KIN  576          // DH + H
#define AA   64

typedef unsigned long long u64;

#define SW128(off) ((off) ^ (((off) >> 3) & 0x70))

// ======================= helpers =======================
__device__ __forceinline__ uint32_t smem_to_u32(const void* p) {
    uint32_t a;
    asm("{ .reg .u64 t; cvta.to.shared.u64 t, %1; cvt.u32.u64 %0, t; }" : "=r"(a) : "l"(p));
    return a;
}
__device__ __forceinline__ void cpa16(uint32_t s, const void* g) {
    asm volatile("cp.async.cg.shared.global [%0], [%1], 16;" :: "r"(s), "l"(g));
}
#define CP_COMMIT() asm volatile("cp.async.commit_group;" ::: "memory")
#define CP_WAIT(n)  asm volatile("cp.async.wait_group %0;" :: "n"(n) : "memory")
__device__ __forceinline__ void ldsm4(uint32_t* r, uint32_t addr) {
    asm volatile("ldmatrix.sync.aligned.m8n8.x4.shared.b16 {%0,%1,%2,%3}, [%4];"
        : "=r"(r[0]), "=r"(r[1]), "=r"(r[2]), "=r"(r[3]) : "r"(addr));
}
__device__ __forceinline__ void mma16816h(float* c, const uint32_t* a, const uint32_t* b) {
    asm volatile("mma.sync.aligned.m16n8k16.row.col.f32.f16.f16.f32 "
        "{%0,%1,%2,%3}, {%4,%5,%6,%7}, {%8,%9}, {%0,%1,%2,%3};"
        : "+f"(c[0]), "+f"(c[1]), "+f"(c[2]), "+f"(c[3])
        : "r"(a[0]), "r"(a[1]), "r"(a[2]), "r"(a[3]), "r"(b[0]), "r"(b[1]));
}
__device__ __forceinline__ u64 pk2(float lo, float hi) {
    u64 r; asm("mov.b64 %0, {%1, %2};" : "=l"(r) : "f"(lo), "f"(hi)); return r;
}
__device__ __forceinline__ float2 upk2(u64 v) {
    float2 f; asm("mov.b64 {%0, %1}, %2;" : "=f"(f.x), "=f"(f.y) : "l"(v)); return f;
}
__device__ __forceinline__ void fma2(u64 &d, u64 a, u64 b) {
    asm("fma.rn.f32x2 %0, %1, %2, %0;" : "+l"(d) : "l"(a), "l"(b));
}
__device__ __forceinline__ float sigf(float x) { return 1.0f / (1.0f + expf(-x)); }

// ======================= scratch (device globals) =======================
__device__ float g_mu1[BT];
__device__ float g_rs1[BT];
__device__ __half g_xph[BT * DH_];              // x (fp16 single plane)
__device__ __half g_wph[2][8][256 * 576];       // [dir][nb][n'(256)*576 + k], n'=nl*4+gate
__device__ __half g_hh[2][2][BB * HH];          // [dir][buf][b*512+n] (fp16 single plane)
__device__ float g_c[2][BB * HH];               // cell state
__device__ float g_hcat[BB * TT * 2 * HH];      // masked concat [b][t][1024]
__device__ float g_mu3[BB];
__device__ float g_rs3[BB];
__device__ unsigned g_bar[32];                  // group barriers (dir*16+Mblk), zero-init

// ---------------- K0: per-row mean / rstd of ud (LN1 stats) ----------------
__global__ void k0_rowstats(const float* __restrict__ ud) {
    int row = blockIdx.x * 8 + threadIdx.y;      // blockDim = (32, 8)
    const float4* p = (const float4*)(ud + (size_t)row * DIN_);
    float s = 0.f, q = 0.f;
    for (int i = threadIdx.x; i < DIN_ / 4; i += 32) {
        float4 v = p[i];
        s += v.x + v.y + v.z + v.w;
        q += v.x * v.x + v.y * v.y + v.z * v.z + v.w * v.w;
    }
    #pragma unroll
    for (int o = 16; o; o >>= 1) {
        s += __shfl_down_sync(0xffffffffu, s, o);
        q += __shfl_down_sync(0xffffffffu, q, o);
    }
    if (threadIdx.x == 0) {
        float mu = s / (float)DIN_;
        float var = q / (float)DIN_ - mu * mu;
        g_mu1[row] = mu;
        g_rs1[row] = rsqrtf(var + 1e-12f);
    }
}

// ---------------- KP: prepack W into fp16, gate-interleaved, K-major ----------------
__global__ void kp_w(const float* __restrict__ Wfw, const float* __restrict__ Wbw) {
    int idx = blockIdx.x * 256 + threadIdx.x;    // 2 * 576 * 2048 total
    int dir = idx >= (KIN * G4);
    int r = idx - dir * (KIN * G4);
    int k = r >> 11;
    int col = r & 2047;
    const float* W = dir ? Wbw : Wfw;
    float v = W[(size_t)k * G4 + col];
    int g = col >> 9, rr = col & 511, nb = rr >> 6, nl = rr & 63;
    int np = nl * 4 + g;
    g_wph[dir][nb][np * 576 + k] = __float2half(v);
}

// ---------------- K1: LN1 -> dense -> LN2 -> relu -> fp16 pack (f32x2 inner) ----------------
__global__ void k1_dense(const float* __restrict__ ud,
                         const float* __restrict__ g1, const float* __restrict__ b1,
                         const float* __restrict__ Wd, const float* __restrict__ bd,
                         const float* __restrict__ g2, const float* __restrict__ b2) {
    __shared__ float As[16][132];
    __shared__ float Bs[16][64];
    __shared__ float buf[128][65];
    __shared__ float smu[128], srs[128];

    int tid = threadIdx.x;
    int bx = blockIdx.x;
    int ty = tid >> 4, tx = tid & 15;

    u64 acc2[4][4];
    #pragma unroll
    for (int p = 0; p < 4; p++)
        #pragma unroll
        for (int j = 0; j < 4; j++) acc2[p][j] = 0ull;

    #pragma unroll 1
    for (int kt = 0; kt < DIN_; kt += 16) {
        #pragma unroll
        for (int it = 0; it < 2; it++) {
            int v = tid + it * 256;
            int r = v >> 2, q = (v & 3) * 4;
            int gr = bx * 128 + r;
            float4 val = *(const float4*)(ud + (size_t)gr * DIN_ + kt + q);
            float mu = g_mu1[gr], rs = g_rs1[gr];
            As[q + 0][r] = (val.x - mu) * rs * g1[kt + q + 0] + b1[kt + q + 0];
            As[q + 1][r] = (val.y - mu) * rs * g1[kt + q + 1] + b1[kt + q + 1];
            As[q + 2][r] = (val.z - mu) * rs * g1[kt + q + 2] + b1[kt + q + 2];
            As[q + 3][r] = (val.w - mu) * rs * g1[kt + q + 3] + b1[kt + q + 3];
        }
        {
            int k = tid >> 4, c0 = (tid & 15) * 4;
            float4 w = *(const float4*)(Wd + (size_t)(kt + k) * 64 + c0);
            Bs[k][c0 + 0] = w.x; Bs[k][c0 + 1] = w.y; Bs[k][c0 + 2] = w.z; Bs[k][c0 + 3] = w.w;
        }
        __syncthreads();
        #pragma unroll
        for (int k = 0; k < 16; k++) {
            const u64* ar = (const u64*)&As[k][ty * 8];
            float4 bv = *(const float4*)&Bs[k][tx * 4];
            u64 b0 = pk2(bv.x, bv.x), b1d = pk2(bv.y, bv.y);
            u64 b2d = pk2(bv.z, bv.z), b3 = pk2(bv.w, bv.w);
            #pragma unroll
            for (int p = 0; p < 4; p++) {
                u64 ap = ar[p];
                fma2(acc2[p][0], ap, b0);
                fma2(acc2[p][1], ap, b1d);
                fma2(acc2[p][2], ap, b2d);
                fma2(acc2[p][3], ap, b3);
            }
        }
        __syncthreads();
    }

    #pragma unroll
    for (int p = 0; p < 4; p++)
        #pragma unroll
        for (int j = 0; j < 4; j++) {
            float2 v = upk2(acc2[p][j]);
            float bb = bd[tx * 4 + j];
            buf[ty * 8 + p * 2 + 0][tx * 4 + j] = v.x + bb;
            buf[ty * 8 + p * 2 + 1][tx * 4 + j] = v.y + bb;
        }
    __syncthreads();
    if (tid < 128) {
        float s = 0.f, q = 0.f;
        #pragma unroll
        for (int c = 0; c < 64; c++) { float v = buf[tid][c]; s += v; q += v * v; }
        float mu = s / 64.f;
        smu[tid] = mu;
        srs[tid] = rsqrtf(q / 64.f - mu * mu + 1e-12f);
    }
    __syncthreads();
    #pragma unroll
    for (int r = 0; r < 8; r++) {
        int lr = ty * 8 + r;
        float mu = smu[lr], rs = srs[lr];
        int gr = bx * 128 + lr;
        #pragma unroll
        for (int j = 0; j < 4; j++) {
            int c = tx * 4 + j;
            float y = (buf[lr][c] - mu) * rs * g2[c] + b2[c];
            g_xph[(size_t)gr * DH_ + c] = __float2half(fmaxf(y, 0.f));
        }
    }
}

// ---------------- K2P: persistent bidirectional LSTM (fp16 single-pass) ----------------
// grid (16 Mblk, 4 nbPair, 2 dir) = 128 CTAs, 512 threads (16 warps).
// CTA tile M=128 x N=256 per half (2 halves/step). K=576 in 9 chunks of 64.
// 4 smem stages x 48KB (A 16K + B 32K), window 3, one syncthreads per chunk,
// cross-step x-prefetch, 4-CTA group barrier, register epilogue via shfl.
__global__ void __launch_bounds__(512, 1)
k2p_persist(const float* __restrict__ bfw, const float* __restrict__ bbw,
            const int* __restrict__ au) {
    extern __shared__ __align__(16) char dsm[];

    int tid = threadIdx.x;
    int wid = tid >> 5, lid = tid & 31;
    int bx = blockIdx.x, npair = blockIdx.y, dir = blockIdx.z;
    int wm = wid & 3, wn = wid >> 2;           // warp grid 4x4 (M x N)
    int grp = dir * 16 + bx;

    uint32_t b32 = smem_to_u32(dsm);
    uint32_t tb32 = (b32 + 1023) & ~1023u;

    const float* bias = dir ? bbw : bfw;

    // ---- cp.async invariants: A (2 units/thread), B (4 units/thread) ----
    uint32_t swA[2]; int gbA[2], qA8[2], aA[2];
    #pragma unroll
    for (int i = 0; i < 2; i++) {
        int idx = tid + i * 512;
        int row = idx >> 3, q = idx & 7;
        swA[i] = SW128((uint32_t)(row * 128 + q * 16));
        gbA[i] = bx * 128 + row;
        qA8[i] = q * 8;
        aA[i] = au[gbA[i]];
    }
    uint32_t swB[4]; int boff[4];
    #pragma unroll
    for (int i = 0; i < 4; i++) {
        int idx = tid + i * 512;
        int row = idx >> 3, q = idx & 7;
        swB[i] = SW128((uint32_t)(row * 128 + q * 16));
        boff[i] = row * KIN + q * 8;
    }

    // ---- ldmatrix invariants ----
    int lar = (lid & 7) + ((lid >> 3) & 1) * 8;
    int lac2 = ((lid >> 4) & 1) * 16;
    int lbr = (lid & 7) + ((lid >> 4) & 1) * 8;
    int lbc2 = ((lid >> 3) & 1) * 16;
    uint32_t aBase[2], aXor[2], bBase[4], bXor[4];
    #pragma unroll
    for (int mt = 0; mt < 2; mt++) {
        int r = wm * 32 + mt * 16 + lar;
        aBase[mt] = (uint32_t)(r * 128);
        aXor[mt] = (uint32_t)((r & 7) << 4);
    }
    #pragma unroll
    for (int np = 0; np < 4; np++) {
        int r = wn * 64 + np * 16 + lbr;
        bBase[np] = (uint32_t)(r * 128);
        bXor[np] = (uint32_t)((r & 7) << 4);
    }

    // ---- epilogue invariants ----
    int l2 = lid & 3;
    int erow[2], ea[2];
    #pragma unroll
    for (int mt = 0; mt < 2; mt++) {
        erow[mt] = wm * 32 + mt * 16 + (lid >> 2) + (l2 & 1) * 8;
        ea[mt] = au[bx * 128 + erow[mt]];
    }

    float acc[2][8][4];
    #pragma unroll
    for (int mt = 0; mt < 2; mt++)
        #pragma unroll
        for (int nt = 0; nt < 8; nt++)
            #pragma unroll
            for (int j = 0; j < 4; j++) acc[mt][nt][j] = 0.f;

    int sbuf = 0, cbuf = 0;

    // issue chunk ci of step t into stage sbuf (NC chunks per half)
    auto issueC = [&](int t, int ci) {
        int NC = (t == 0) ? 1 : 9;
        int half = (ci >= NC) ? 1 : 0;
        int kc = ci - half * NC;
        uint32_t sb = tb32 + (uint32_t)sbuf * 49152u;
        if (kc == 0) {
            #pragma unroll
            for (int i = 0; i < 2; i++) {
                int ts = t;
                if (dir) ts = (t < aA[i]) ? (aA[i] - 1 - t) : t;
                cpa16(sb + swA[i], g_xph + (gbA[i] * TT + ts) * DH_ + qA8[i]);
            }
        } else {
            const __half* hp = g_hh[dir][(t & 1) ^ 1];
            int e0 = (kc - 1) * 64;
            #pragma unroll
            for (int i = 0; i < 2; i++)
                cpa16(sb + swA[i], hp + gbA[i] * HH + e0 + qA8[i]);
        }
        int nb = npair * 2 + half;
        const __half* wp = g_wph[dir][nb];
        int ke = kc * 64;
        #pragma unroll
        for (int i = 0; i < 4; i++)
            cpa16(sb + 16384 + swB[i], wp + boff[i] + ke);
        CP_COMMIT();
        sbuf = (sbuf + 1) & 3;
    };

    int pending = 0;

    #pragma unroll 1
    for (int t = 0; t < TT; t++) {
        int NC = (t == 0) ? 1 : 9;
        int NC2 = 2 * NC;

        int issued = pending;
        while (issued < NC2 && issued < 3) { issueC(t, issued); issued++; }

        #pragma unroll 1
        for (int ci = 0; ci < NC2; ci++) {
            int ahead = issued - ci;
            if (ahead >= 3)      CP_WAIT(2);
            else if (ahead == 2) CP_WAIT(1);
            else                 CP_WAIT(0);
            __syncthreads();
            if (issued < NC2) { issueC(t, issued); issued++; }

            uint32_t sb = tb32 + (uint32_t)cbuf * 49152u;
            cbuf = (cbuf + 1) & 3;

            #pragma unroll
            for (int kt = 0; kt < 4; kt++) {
                uint32_t ah[2][4], bf[4][4];
                #pragma unroll
                for (int mt = 0; mt < 2; mt++) {
                    uint32_t cb = ((uint32_t)(kt * 32 + lac2)) ^ aXor[mt];
                    ldsm4(ah[mt], sb + aBase[mt] + cb);
                }
                #pragma unroll
                for (int np = 0; np < 4; np++) {
                    uint32_t cb = ((uint32_t)(kt * 32 + lbc2)) ^ bXor[np];
                    ldsm4(bf[np], sb + 16384 + bBase[np] + cb);
                }
                #pragma unroll
                for (int mt = 0; mt < 2; mt++)
                    #pragma unroll
                    for (int nt = 0; nt < 8; nt++)
                        mma16816h(acc[mt][nt], ah[mt], &bf[nt >> 1][(nt & 1) * 2]);
            }

            // ---- end of half: LSTM cell epilogue ----
            if (ci == NC - 1 || ci == NC2 - 1) {
                int half = (ci >= NC) ? 1 : 0;
                int nb = npair * 2 + half;
                bool oddl = (l2 & 1);
                __half* ohh = g_hh[dir][t & 1];
                #pragma unroll
                for (int mt = 0; mt < 2; mt++) {
                    int row = erow[mt];
                    int gb = bx * 128 + row;
                    int a0 = ea[mt];
                    bool m = (t < a0);
                    float* cptr = g_c[dir] + (size_t)gb * HH + nb * 64;
                    size_t hb = (size_t)gb * HH + nb * 64;
                    size_t hc;
                    if (dir == 0) hc = ((size_t)gb * TT + t) * (2 * HH) + nb * 64;
                    else {
                        int dst = m ? (a0 - 1 - t) : t;
                        hc = ((size_t)gb * TT + dst) * (2 * HH) + HH + nb * 64;
                    }
                    #pragma unroll
                    for (int nt = 0; nt < 8; nt++) {
                        float o0 = acc[mt][nt][0], o1 = acc[mt][nt][1];
                        float o2 = acc[mt][nt][2], o3 = acc[mt][nt][3];
                        float r0 = __shfl_xor_sync(0xffffffffu, o0, 1);
                        float r1 = __shfl_xor_sync(0xffffffffu, o1, 1);
                        float r2 = __shfl_xor_sync(0xffffffffu, o2, 1);
                        float r3 = __shfl_xor_sync(0xffffffffu, o3, 1);
                        float zi, zj, zf, zo;
                        if (!oddl) { zi = o0; zj = o1; zf = r0; zo = r1; }
                        else       { zi = r2; zj = r3; zf = o2; zo = o3; }
                        int u = wn * 16 + nt * 2 + (l2 >> 1);
                        int n = nb * 64 + u;
                        float vi = zi + bias[n];
                        float vj = zj + bias[HH + n];
                        float vf = zf + bias[2 * HH + n];
                        float vo = zo + bias[3 * HH + n];
                        float cp = (t == 0) ? 0.f : cptr[u];
                        float cn = cp * sigf(vf + 1.0f) + sigf(vi) * tanhf(vj);
                        float hn = tanhf(cn) * sigf(vo);
                        cptr[u] = cn;
                        ohh[hb + u] = __float2half(hn);
                        g_hcat[hc + u] = m ? hn : 0.f;
                    }
                }
                #pragma unroll
                for (int mt = 0; mt < 2; mt++)
                    #pragma unroll
                    for (int nt = 0; nt < 8; nt++)
                        #pragma unroll
                        for (int j = 0; j < 4; j++) acc[mt][nt][j] = 0.f;
            }
        }

        // ---- cross-step x prefetch + inter-step group barrier ----
        if (t < TT - 1) {
            issueC(t + 1, 0);
            pending = 1;
            __syncthreads();
            if (tid == 0) {
                __threadfence();
                atomicAdd(&g_bar[grp], 1u);
                unsigned target = 4u * (unsigned)(t + 1);
                while (atomicAdd(&g_bar[grp], 0u) < target) __nanosleep(64);
            }
            __syncthreads();
        }
    }

    // final arrival + reset for graph-replay determinism
    __syncthreads();
    if (tid == 0) {
        __threadfence();
        atomicAdd(&g_bar[grp], 1u);
        if (npair == 0) {
            while (atomicAdd(&g_bar[grp], 0u) < 4u * (unsigned)TT) __nanosleep(64);
            g_bar[grp] = 0u;
            __threadfence();
        }
    }
}

// ---------------- K3: per-batch LN3 stats over (T, 2H) ----------------
__global__ void k3_stats() {
    __shared__ float ssum[256], ssq[256];
    int b = blockIdx.x, tid = threadIdx.x;
    const float4* p = (const float4*)(g_hcat + (size_t)b * (TT * 2 * HH));
    float s = 0.f, q = 0.f;
    for (int i = tid; i < (TT * 2 * HH) / 4; i += 256) {
        float4 v = p[i];
        s += v.x + v.y + v.z + v.w;
        q += v.x * v.x + v.y * v.y + v.z * v.z + v.w * v.w;
    }
    ssum[tid] = s; ssq[tid] = q;
    __syncthreads();
    for (int o = 128; o; o >>= 1) {
        if (tid < o) { ssum[tid] += ssum[tid + o]; ssq[tid] += ssq[tid + o]; }
        __syncthreads();
    }
    if (tid == 0) {
        float mu = ssum[0] / 32768.f;
        g_mu3[b] = mu;
        g_rs3[b] = rsqrtf(ssq[0] / 32768.f - mu * mu + 1e-12f);
    }
}

// ---------------- K4: relu(LN3) -> conv matmul -> tanh (f32x2 inner) ----------------
__global__ void k4_out(const float* __restrict__ g3, const float* __restrict__ b3,
                       const float* __restrict__ Wc, const float* __restrict__ bc,
                       float* __restrict__ out) {
    __shared__ float As[16][132];
    __shared__ float Bs[16][64];

    int tid = threadIdx.x;
    int bx = blockIdx.x;
    int ty = tid >> 4, tx = tid & 15;

    u64 acc2[4][4];
    #pragma unroll
    for (int p = 0; p < 4; p++)
        #pragma unroll
        for (int j = 0; j < 4; j++) acc2[p][j] = 0ull;

    #pragma unroll 1
    for (int kt = 0; kt < 2 * HH; kt += 16) {
        #pragma unroll
        for (int it = 0; it < 2; it++) {
            int v = tid + it * 256;
            int r = v >> 2, q = (v & 3) * 4;
            int gr = bx * 128 + r;
            int bat = gr >> 5;
            float4 val = *(const float4*)(g_hcat + (size_t)gr * (2 * HH) + kt + q);
            float mu = g_mu3[bat], rs = g_rs3[bat];
            As[q + 0][r] = fmaxf((val.x - mu) * rs * g3[kt + q + 0] + b3[kt + q + 0], 0.f);
            As[q + 1][r] = fmaxf((val.y - mu) * rs * g3[kt + q + 1] + b3[kt + q + 1], 0.f);
            As[q + 2][r] = fmaxf((val.z - mu) * rs * g3[kt + q + 2] + b3[kt + q + 2], 0.f);
            As[q + 3][r] = fmaxf((val.w - mu) * rs * g3[kt + q + 3] + b3[kt + q + 3], 0.f);
        }
        {
            int k = tid >> 4, c0 = (tid & 15) * 4;
            float4 w = *(const float4*)(Wc + (size_t)(kt + k) * AA + c0);
            Bs[k][c0 + 0] = w.x; Bs[k][c0 + 1] = w.y; Bs[k][c0 + 2] = w.z; Bs[k][c0 + 3] = w.w;
        }
        __syncthreads();
        #pragma unroll
        for (int k = 0; k < 16; k++) {
            const u64* ar = (const u64*)&As[k][ty * 8];
            float4 bv = *(const float4*)&Bs[k][tx * 4];
            u64 b0 = pk2(bv.x, bv.x), b1d = pk2(bv.y, bv.y);
            u64 b2d = pk2(bv.z, bv.z), b3d = pk2(bv.w, bv.w);
            #pragma unroll
            for (int p = 0; p < 4; p++) {
                u64 ap = ar[p];
                fma2(acc2[p][0], ap, b0);
                fma2(acc2[p][1], ap, b1d);
                fma2(acc2[p][2], ap, b2d);
                fma2(acc2[p][3], ap, b3d);
            }
        }
        __syncthreads();
    }

    #pragma unroll
    for (int p = 0; p < 4; p++) {
        int gr0 = bx * 128 + ty * 8 + p * 2;
        #pragma unroll
        for (int j = 0; j < 4; j++) {
            float2 v = upk2(acc2[p][j]);
            int c = tx * 4 + j;
            out[(size_t)gr0 * AA + c]       = tanhf(v.x + bc[c]);
            out[(size_t)(gr0 + 1) * AA + c] = tanhf(v.y + bc[c]);
        }
    }
}

// ---------------- launch ----------------
extern "C" void kernel_launch(void* const* d_in, const int* in_sizes, int n_in,
                              void* d_out, int out_size) {
    int s = (n_in >= 18) ? 1 : 0;
    const float* ud  = (const float*)d_in[0];
    const int*   au  = (const int*)  d_in[2];
    const float* g1  = (const float*)d_in[3 + s];
    const float* b1  = (const float*)d_in[4 + s];
    const float* Wd  = (const float*)d_in[5 + s];
    const float* bd  = (const float*)d_in[6 + s];
    const float* g2  = (const float*)d_in[7 + s];
    const float* b2  = (const float*)d_in[8 + s];
    const float* Wfw = (const float*)d_in[9 + s];
    const float* bfw = (const float*)d_in[10 + s];
    const float* Wbw = (const float*)d_in[11 + s];
    const float* bbw = (const float*)d_in[12 + s];
    const float* g3  = (const float*)d_in[13 + s];
    const float* b3  = (const float*)d_in[14 + s];
    const float* Wc  = (const float*)d_in[15 + s];
    const float* bc  = (const float*)d_in[16 + s];
    float* out = (float*)d_out;

    const int K2_SMEM = 4 * 49152 + 1024;   // 197632 bytes dynamic
    cudaFuncSetAttribute(k2p_persist, cudaFuncAttributeMaxDynamicSharedMemorySize, K2_SMEM);

    kp_w<<<(2 * KIN * G4) / 256, 256>>>(Wfw, Wbw);
    k0_rowstats<<<BT / 8, dim3(32, 8)>>>(ud);
    k1_dense<<<BT / 128, 256>>>(ud, g1, b1, Wd, bd, g2, b2);
    k2p_persist<<<dim3(16, 4, 2), 512, K2_SMEM>>>(bfw, bbw, au);
    k3_stats<<<BB, 256>>>();
    k4_out<<<BT / 128, 256>>>(g3, b3, Wc, bc, out);
}

// round 7
// speedup vs baseline: 5.1796x; 1.8690x over previous
#include <cuda_runtime.h>
#include <cuda_fp16.h>
#include <math.h>
#include <stdint.h>

// Problem constants
#define BB   2048
#define TT   32
#define BT   65536        // BB*TT
#define DIN_ 1024
#define DH_  64
#define HH   512
#define G4   2048         // 4*H
#define KIN  576          // DH + H
#define AA   64

typedef unsigned long long u64;

#define SW128(off) ((off) ^ (((off) >> 3) & 0x70))

// ======================= helpers =======================
__device__ __forceinline__ uint32_t smem_to_u32(const void* p) {
    uint32_t a;
    asm("{ .reg .u64 t; cvta.to.shared.u64 t, %1; cvt.u32.u64 %0, t; }" : "=r"(a) : "l"(p));
    return a;
}
__device__ __forceinline__ void cpa16(uint32_t s, const void* g) {
    asm volatile("cp.async.cg.shared.global [%0], [%1], 16;" :: "r"(s), "l"(g));
}
#define CP_COMMIT() asm volatile("cp.async.commit_group;" ::: "memory")
#define CP_WAIT(n)  asm volatile("cp.async.wait_group %0;" :: "n"(n) : "memory")
__device__ __forceinline__ void ldsm4(uint32_t* r, uint32_t addr) {
    asm volatile("ldmatrix.sync.aligned.m8n8.x4.shared.b16 {%0,%1,%2,%3}, [%4];"
        : "=r"(r[0]), "=r"(r[1]), "=r"(r[2]), "=r"(r[3]) : "r"(addr));
}
__device__ __forceinline__ void mma16816h(float* c, const uint32_t* a, const uint32_t* b) {
    asm volatile("mma.sync.aligned.m16n8k16.row.col.f32.f16.f16.f32 "
        "{%0,%1,%2,%3}, {%4,%5,%6,%7}, {%8,%9}, {%0,%1,%2,%3};"
        : "+f"(c[0]), "+f"(c[1]), "+f"(c[2]), "+f"(c[3])
        : "r"(a[0]), "r"(a[1]), "r"(a[2]), "r"(a[3]), "r"(b[0]), "r"(b[1]));
}
__device__ __forceinline__ u64 pk2(float lo, float hi) {
    u64 r; asm("mov.b64 %0, {%1, %2};" : "=l"(r) : "f"(lo), "f"(hi)); return r;
}
__device__ __forceinline__ float2 upk2(u64 v) {
    float2 f; asm("mov.b64 {%0, %1}, %2;" : "=f"(f.x), "=f"(f.y) : "l"(v)); return f;
}
__device__ __forceinline__ void fma2(u64 &d, u64 a, u64 b) {
    asm("fma.rn.f32x2 %0, %1, %2, %0;" : "+l"(d) : "l"(a), "l"(b));
}
// fast gates via MUFU (rel err ~1e-6, negligible vs fp16 GEMM noise)
__device__ __forceinline__ float fsig(float x)  { return __fdividef(1.f, 1.f + __expf(-x)); }
__device__ __forceinline__ float ftanh(float x) { return 1.f - __fdividef(2.f, __expf(2.f * x) + 1.f); }

// ======================= scratch (device globals) =======================
__device__ float g_mu1[BT];
__device__ float g_rs1[BT];
__device__ __half g_xph[BT * DH_];               // x (fp16)  [(b*T+t)*64+d]
__device__ __half g_wph[2][8][256 * 576];        // [dir][nb][n'(256)*576 + k], n'=nl*4+gate
__device__ __half g_hh[2][2][BB * HH];           // [dir][buf][b*512+n]
__device__ float g_hcatT[2 * HH * TT * BB];      // [h(1024)][t(32)][b(2048)], RAW t both dirs
__device__ float g_P[BT * AA];                   // fw partial  [b][t][a]
__device__ float g_Q[BT * AA];                   // bw partial (raw t)  [b][t][a]
__device__ float g_mu3[BB];
__device__ float g_rs3[BB];
__device__ float g_p3s[16 * BB];
__device__ float g_p3q[16 * BB];
__device__ unsigned g_bar[32];                   // group barriers (dir*16+Mblk), zero-init

// ---------------- K0: per-row mean / rstd of ud (LN1 stats) ----------------
__global__ void k0_rowstats(const float* __restrict__ ud) {
    int row = blockIdx.x * 8 + threadIdx.y;      // blockDim = (32, 8)
    const float4* p = (const float4*)(ud + (size_t)row * DIN_);
    float s = 0.f, q = 0.f;
    for (int i = threadIdx.x; i < DIN_ / 4; i += 32) {
        float4 v = p[i];
        s += v.x + v.y + v.z + v.w;
        q += v.x * v.x + v.y * v.y + v.z * v.z + v.w * v.w;
    }
    #pragma unroll
    for (int o = 16; o; o >>= 1) {
        s += __shfl_down_sync(0xffffffffu, s, o);
        q += __shfl_down_sync(0xffffffffu, q, o);
    }
    if (threadIdx.x == 0) {
        float mu = s / (float)DIN_;
        float var = q / (float)DIN_ - mu * mu;
        g_mu1[row] = mu;
        g_rs1[row] = rsqrtf(var + 1e-12f);
    }
}

// ---------------- KP: prepack W into fp16, gate-interleaved, K-major ----------------
__global__ void kp_w(const float* __restrict__ Wfw, const float* __restrict__ Wbw) {
    int idx = blockIdx.x * 256 + threadIdx.x;    // 2 * 576 * 2048 total
    int dir = idx >= (KIN * G4);
    int r = idx - dir * (KIN * G4);
    int k = r >> 11;
    int col = r & 2047;
    const float* W = dir ? Wbw : Wfw;
    float v = W[(size_t)k * G4 + col];
    int g = col >> 9, rr = col & 511, nb = rr >> 6, nl = rr & 63;
    int np = nl * 4 + g;
    g_wph[dir][nb][np * 576 + k] = __float2half(v);
}

// ---------------- K1: LN1 -> dense -> LN2 -> relu -> fp16 pack (f32x2 inner) ----------------
__global__ void k1_dense(const float* __restrict__ ud,
                         const float* __restrict__ g1, const float* __restrict__ b1,
                         const float* __restrict__ Wd, const float* __restrict__ bd,
                         const float* __restrict__ g2, const float* __restrict__ b2) {
    __shared__ float As[16][132];
    __shared__ float Bs[16][64];
    __shared__ float buf[128][65];
    __shared__ float smu[128], srs[128];

    int tid = threadIdx.x;
    int bx = blockIdx.x;
    int ty = tid >> 4, tx = tid & 15;

    u64 acc2[4][4];
    #pragma unroll
    for (int p = 0; p < 4; p++)
        #pragma unroll
        for (int j = 0; j < 4; j++) acc2[p][j] = 0ull;

    #pragma unroll 1
    for (int kt = 0; kt < DIN_; kt += 16) {
        #pragma unroll
        for (int it = 0; it < 2; it++) {
            int v = tid + it * 256;
            int r = v >> 2, q = (v & 3) * 4;
            int gr = bx * 128 + r;
            float4 val = *(const float4*)(ud + (size_t)gr * DIN_ + kt + q);
            float mu = g_mu1[gr], rs = g_rs1[gr];
            As[q + 0][r] = (val.x - mu) * rs * g1[kt + q + 0] + b1[kt + q + 0];
            As[q + 1][r] = (val.y - mu) * rs * g1[kt + q + 1] + b1[kt + q + 1];
            As[q + 2][r] = (val.z - mu) * rs * g1[kt + q + 2] + b1[kt + q + 2];
            As[q + 3][r] = (val.w - mu) * rs * g1[kt + q + 3] + b1[kt + q + 3];
        }
        {
            int k = tid >> 4, c0 = (tid & 15) * 4;
            float4 w = *(const float4*)(Wd + (size_t)(kt + k) * 64 + c0);
            Bs[k][c0 + 0] = w.x; Bs[k][c0 + 1] = w.y; Bs[k][c0 + 2] = w.z; Bs[k][c0 + 3] = w.w;
        }
        __syncthreads();
        #pragma unroll
        for (int k = 0; k < 16; k++) {
            const u64* ar = (const u64*)&As[k][ty * 8];
            float4 bv = *(const float4*)&Bs[k][tx * 4];
            u64 b0 = pk2(bv.x, bv.x), b1d = pk2(bv.y, bv.y);
            u64 b2d = pk2(bv.z, bv.z), b3 = pk2(bv.w, bv.w);
            #pragma unroll
            for (int p = 0; p < 4; p++) {
                u64 ap = ar[p];
                fma2(acc2[p][0], ap, b0);
                fma2(acc2[p][1], ap, b1d);
                fma2(acc2[p][2], ap, b2d);
                fma2(acc2[p][3], ap, b3);
            }
        }
        __syncthreads();
    }

    #pragma unroll
    for (int p = 0; p < 4; p++)
        #pragma unroll
        for (int j = 0; j < 4; j++) {
            float2 v = upk2(acc2[p][j]);
            float bb = bd[tx * 4 + j];
            buf[ty * 8 + p * 2 + 0][tx * 4 + j] = v.x + bb;
            buf[ty * 8 + p * 2 + 1][tx * 4 + j] = v.y + bb;
        }
    __syncthreads();
    if (tid < 128) {
        float s = 0.f, q = 0.f;
        #pragma unroll
        for (int c = 0; c < 64; c++) { float v = buf[tid][c]; s += v; q += v * v; }
        float mu = s / 64.f;
        smu[tid] = mu;
        srs[tid] = rsqrtf(q / 64.f - mu * mu + 1e-12f);
    }
    __syncthreads();
    #pragma unroll
    for (int r = 0; r < 8; r++) {
        int lr = ty * 8 + r;
        float mu = smu[lr], rs = srs[lr];
        int gr = bx * 128 + lr;
        #pragma unroll
        for (int j = 0; j < 4; j++) {
            int c = tx * 4 + j;
            float y = (buf[lr][c] - mu) * rs * g2[c] + b2[c];
            g_xph[(size_t)gr * DH_ + c] = __float2half(fmaxf(y, 0.f));
        }
    }
}

// ---------------- K2P: persistent bidirectional LSTM (fp16, smem c, coalesced outputs) ----------------
// grid (16 Mblk, 4 nbPair, 2 dir) = 128 CTAs, 512 threads (16 warps).
// CTA tile M=128 x N=256 per half (2 halves/step). K=576 in 9 chunks of 64.
// 3 smem stages x 48KB + c-state 66KB + h-stage 17KB. Window 2.
// hcatT written at RAW t for both dirs (coalesced); reversal handled in k4b.
__global__ void __launch_bounds__(512, 1)
k2p_persist(const float* __restrict__ bfw, const float* __restrict__ bbw,
            const int* __restrict__ au) {
    extern __shared__ __align__(16) char dsm[];

    int tid = threadIdx.x;
    int wid = tid >> 5, lid = tid & 31;
    int bx = blockIdx.x, npair = blockIdx.y, dir = blockIdx.z;
    int wm = wid & 3, wn = wid >> 2;           // warp grid 4x4 (M x N)
    int grp = dir * 16 + bx;

    uint32_t b32 = smem_to_u32(dsm);
    uint32_t tb32 = (b32 + 1023) & ~1023u;
    char* tb = dsm + (tb32 - b32);
    float* cS = (float*)(tb + 147456);            // c-state [128][129] f32
    char*  hst = tb + 147456 + 66048;             // h-stage [128][68] fp16

    const float* bias = dir ? bbw : bfw;

    // ---- cp.async invariants: A (2 units/thread), B (4 units/thread) ----
    uint32_t swA[2]; int gbA[2], qA8[2], aA[2];
    #pragma unroll
    for (int i = 0; i < 2; i++) {
        int idx = tid + i * 512;
        int row = idx >> 3, q = idx & 7;
        swA[i] = SW128((uint32_t)(row * 128 + q * 16));
        gbA[i] = bx * 128 + row;
        qA8[i] = q * 8;
        aA[i] = au[gbA[i]];
    }
    uint32_t swB[4]; int boff[4];
    #pragma unroll
    for (int i = 0; i < 4; i++) {
        int idx = tid + i * 512;
        int row = idx >> 3, q = idx & 7;
        swB[i] = SW128((uint32_t)(row * 128 + q * 16));
        boff[i] = row * KIN + q * 8;
    }

    // ---- ldmatrix invariants ----
    int lar = (lid & 7) + ((lid >> 3) & 1) * 8;
    int lac2 = ((lid >> 4) & 1) * 16;
    int lbr = (lid & 7) + ((lid >> 4) & 1) * 8;
    int lbc2 = ((lid >> 3) & 1) * 16;
    uint32_t aBase[2], aXor[2], bBase[4], bXor[4];
    #pragma unroll
    for (int mt = 0; mt < 2; mt++) {
        int r = wm * 32 + mt * 16 + lar;
        aBase[mt] = (uint32_t)(r * 128);
        aXor[mt] = (uint32_t)((r & 7) << 4);
    }
    #pragma unroll
    for (int np = 0; np < 4; np++) {
        int r = wn * 64 + np * 16 + lbr;
        bBase[np] = (uint32_t)(r * 128);
        bXor[np] = (uint32_t)((r & 7) << 4);
    }

    // ---- epilogue invariants ----
    int l2 = lid & 3;
    int erow[2], ea[2];
    #pragma unroll
    for (int mt = 0; mt < 2; mt++) {
        erow[mt] = wm * 32 + mt * 16 + (lid >> 2) + (l2 & 1) * 8;
        ea[mt] = au[bx * 128 + erow[mt]];
    }

    float acc[2][8][4];
    #pragma unroll
    for (int mt = 0; mt < 2; mt++)
        #pragma unroll
        for (int nt = 0; nt < 8; nt++)
            #pragma unroll
            for (int j = 0; j < 4; j++) acc[mt][nt][j] = 0.f;

    int sbuf = 0, cbuf = 0;

    // issue chunk ci of step t into stage sbuf (NC chunks per half)
    auto issueC = [&](int t, int ci) {
        int NC = (t == 0) ? 1 : 9;
        int half = (ci >= NC) ? 1 : 0;
        int kc = ci - half * NC;
        uint32_t sb = tb32 + (uint32_t)sbuf * 49152u;
        if (kc == 0) {
            #pragma unroll
            for (int i = 0; i < 2; i++) {
                int ts = t;
                if (dir) ts = (t < aA[i]) ? (aA[i] - 1 - t) : t;
                cpa16(sb + swA[i], g_xph + (gbA[i] * TT + ts) * DH_ + qA8[i]);
            }
        } else {
            const __half* hp = g_hh[dir][(t & 1) ^ 1];
            int e0 = (kc - 1) * 64;
            #pragma unroll
            for (int i = 0; i < 2; i++)
                cpa16(sb + swA[i], hp + gbA[i] * HH + e0 + qA8[i]);
        }
        int nb = npair * 2 + half;
        const __half* wp = g_wph[dir][nb];
        int ke = kc * 64;
        #pragma unroll
        for (int i = 0; i < 4; i++)
            cpa16(sb + 16384 + swB[i], wp + boff[i] + ke);
        CP_COMMIT();
        sbuf = (sbuf == 2) ? 0 : sbuf + 1;
    };

    int pending = 0;

    #pragma unroll 1
    for (int t = 0; t < TT; t++) {
        int NC = (t == 0) ? 1 : 9;
        int NC2 = 2 * NC;

        int issued = pending;
        while (issued < NC2 && issued < 2) { issueC(t, issued); issued++; }

        #pragma unroll 1
        for (int ci = 0; ci < NC2; ci++) {
            if (issued - ci >= 2) CP_WAIT(1);
            else                  CP_WAIT(0);
            __syncthreads();
            if (issued < NC2) { issueC(t, issued); issued++; }

            uint32_t sb = tb32 + (uint32_t)cbuf * 49152u;
            cbuf = (cbuf == 2) ? 0 : cbuf + 1;

            #pragma unroll
            for (int kt = 0; kt < 4; kt++) {
                uint32_t ah[2][4], bf[4][4];
                #pragma unroll
                for (int mt = 0; mt < 2; mt++) {
                    uint32_t cb = ((uint32_t)(kt * 32 + lac2)) ^ aXor[mt];
                    ldsm4(ah[mt], sb + aBase[mt] + cb);
                }
                #pragma unroll
                for (int np = 0; np < 4; np++) {
                    uint32_t cb = ((uint32_t)(kt * 32 + lbc2)) ^ bXor[np];
                    ldsm4(bf[np], sb + 16384 + bBase[np] + cb);
                }
                #pragma unroll
                for (int mt = 0; mt < 2; mt++)
                    #pragma unroll
                    for (int nt = 0; nt < 8; nt++)
                        mma16816h(acc[mt][nt], ah[mt], &bf[nt >> 1][(nt & 1) * 2]);
            }

            // ---- end of half: LSTM cell epilogue (c in smem, coalesced outputs) ----
            if (ci == NC - 1 || ci == NC2 - 1) {
                int half = (ci >= NC) ? 1 : 0;
                int nb = npair * 2 + half;
                bool oddl = (l2 & 1);
                #pragma unroll
                for (int mt = 0; mt < 2; mt++) {
                    int row = erow[mt];
                    int gb = bx * 128 + row;
                    float mk = (t < ea[mt]) ? 1.f : 0.f;
                    #pragma unroll
                    for (int nt = 0; nt < 8; nt++) {
                        float o0 = acc[mt][nt][0], o1 = acc[mt][nt][1];
                        float o2 = acc[mt][nt][2], o3 = acc[mt][nt][3];
                        float r0 = __shfl_xor_sync(0xffffffffu, o0, 1);
                        float r1 = __shfl_xor_sync(0xffffffffu, o1, 1);
                        float r2 = __shfl_xor_sync(0xffffffffu, o2, 1);
                        float r3 = __shfl_xor_sync(0xffffffffu, o3, 1);
                        float zi, zj, zf, zo;
                        if (!oddl) { zi = o0; zj = o1; zf = r0; zo = r1; }
                        else       { zi = r2; zj = r3; zf = o2; zo = o3; }
                        int u = wn * 16 + nt * 2 + (l2 >> 1);
                        int n = nb * 64 + u;
                        float vi = zi + bias[n];
                        float vj = zj + bias[HH + n];
                        float vf = zf + bias[2 * HH + n];
                        float vo = zo + bias[3 * HH + n];
                        int cidx = row * 129 + half * 64 + u;
                        float cp = (t == 0) ? 0.f : cS[cidx];
                        float cn = cp * fsig(vf + 1.0f) + fsig(vi) * ftanh(vj);
                        float hn = ftanh(cn) * fsig(vo);
                        cS[cidx] = cn;
                        *(__half*)(hst + (row * 68 + u) * 2) = __float2half(hn);
                        // coalesced: [h][t][b], RAW t for both dirs
                        g_hcatT[((size_t)(dir * HH + n) * TT + t) * BB + gb] = hn * mk;
                    }
                }
                #pragma unroll
                for (int mt = 0; mt < 2; mt++)
                    #pragma unroll
                    for (int nt = 0; nt < 8; nt++)
                        #pragma unroll
                        for (int j = 0; j < 4; j++) acc[mt][nt][j] = 0.f;

                __syncthreads();
                // coalesced copy h-stage -> g_hh[dir][t&1] (16KB per half, 8B units)
                __half* oh = g_hh[dir][t & 1];
                #pragma unroll
                for (int i = 0; i < 4; i++) {
                    int idx = tid + i * 512;
                    int row = idx >> 4, ch = idx & 15;
                    u64 v = *(const u64*)(hst + row * 136 + ch * 8);
                    *(u64*)((char*)oh + ((size_t)(bx * 128 + row) * HH + nb * 64 + ch * 4) * 2) = v;
                }
            }
        }

        // ---- cross-step x prefetch + inter-step group barrier ----
        if (t < TT - 1) {
            issueC(t + 1, 0);
            pending = 1;
            __threadfence();
            __syncthreads();
            if (tid == 0) {
                atomicAdd(&g_bar[grp], 1u);
                unsigned target = 4u * (unsigned)(t + 1);
                while (atomicAdd(&g_bar[grp], 0u) < target) __nanosleep(64);
            }
            __syncthreads();
        }
    }

    // final arrival + reset for graph-replay determinism
    __threadfence();
    __syncthreads();
    if (tid == 0) {
        atomicAdd(&g_bar[grp], 1u);
        if (npair == 0) {
            while (atomicAdd(&g_bar[grp], 0u) < 4u * (unsigned)TT) __nanosleep(64);
            g_bar[grp] = 0u;
            __threadfence();
        }
    }
}

// ---------------- K3A: partial LN3 sums over hcatT row-chunks ----------------
__global__ void k3a_part() {
    int bc = blockIdx.x;                 // 8 b-chunks of 256
    int rc = blockIdx.y;                 // 16 row-chunks of 2048 (rows = h*32+t)
    int tid = threadIdx.x;               // 256
    const float* base = g_hcatT + (size_t)rc * 2048 * BB + bc * 256 + tid;
    float s = 0.f, q = 0.f;
    #pragma unroll 8
    for (int i = 0; i < 2048; i++) {
        float v = base[(size_t)i * BB];
        s += v; q += v * v;
    }
    g_p3s[rc * BB + bc * 256 + tid] = s;
    g_p3q[rc * BB + bc * 256 + tid] = q;
}

// ---------------- K3B: reduce partials -> mu3 / rs3 ----------------
__global__ void k3b_reduce() {
    int b = blockIdx.x * 256 + threadIdx.x;
    float s = 0.f, q = 0.f;
    #pragma unroll
    for (int i = 0; i < 16; i++) { s += g_p3s[i * BB + b]; q += g_p3q[i * BB + b]; }
    float mu = s / 32768.f;
    g_mu3[b] = mu;
    g_rs3[b] = rsqrtf(q / 32768.f - mu * mu + 1e-12f);
}

// ---------------- K4A: relu(LN3(hcatT)) @ Wc -> P (fw) and Q (bw raw-t) ----------------
// grid (16 b-blocks, 32 t), 256 threads. A^T GEMM: tile [16 h][128 b].
__global__ void k4a_gemm(const float* __restrict__ g3, const float* __restrict__ b3,
                         const float* __restrict__ Wc) {
    __shared__ float As[16][132];
    __shared__ float Bs[16][64];

    int tid = threadIdx.x;
    int bb = blockIdx.x, t = blockIdx.y;
    int ty = tid >> 4, tx = tid & 15;

    u64 accP[4][4], accQ[4][4];
    #pragma unroll
    for (int p = 0; p < 4; p++)
        #pragma unroll
        for (int j = 0; j < 4; j++) { accP[p][j] = 0ull; accQ[p][j] = 0ull; }

    #pragma unroll 1
    for (int phase = 0; phase < 2; phase++) {
        #pragma unroll 1
        for (int kt = 0; kt < HH; kt += 16) {
            int h0 = phase * HH + kt;
            #pragma unroll
            for (int it = 0; it < 2; it++) {
                int v = tid + it * 256;
                int hl = v >> 5, c4 = v & 31;
                float4 x = *(const float4*)(g_hcatT + (size_t)(h0 + hl) * (TT * BB)
                                            + (size_t)t * BB + bb * 128 + c4 * 4);
                float4 mu = *(const float4*)(g_mu3 + bb * 128 + c4 * 4);
                float4 rs = *(const float4*)(g_rs3 + bb * 128 + c4 * 4);
                float gg = g3[h0 + hl], bg = b3[h0 + hl];
                As[hl][c4 * 4 + 0] = fmaxf((x.x - mu.x) * rs.x * gg + bg, 0.f);
                As[hl][c4 * 4 + 1] = fmaxf((x.y - mu.y) * rs.y * gg + bg, 0.f);
                As[hl][c4 * 4 + 2] = fmaxf((x.z - mu.z) * rs.z * gg + bg, 0.f);
                As[hl][c4 * 4 + 3] = fmaxf((x.w - mu.w) * rs.w * gg + bg, 0.f);
            }
            {
                int k = tid >> 4, c0 = (tid & 15) * 4;
                float4 w = *(const float4*)(Wc + (size_t)(h0 + k) * AA + c0);
                Bs[k][c0 + 0] = w.x; Bs[k][c0 + 1] = w.y; Bs[k][c0 + 2] = w.z; Bs[k][c0 + 3] = w.w;
            }
            __syncthreads();
            #pragma unroll
            for (int k = 0; k < 16; k++) {
                const u64* ar = (const u64*)&As[k][ty * 8];
                float4 bv = *(const float4*)&Bs[k][tx * 4];
                u64 b0 = pk2(bv.x, bv.x), b1d = pk2(bv.y, bv.y);
                u64 b2d = pk2(bv.z, bv.z), b3d = pk2(bv.w, bv.w);
                if (phase == 0) {
                    #pragma unroll
                    for (int p = 0; p < 4; p++) {
                        u64 ap = ar[p];
                        fma2(accP[p][0], ap, b0);
                        fma2(accP[p][1], ap, b1d);
                        fma2(accP[p][2], ap, b2d);
                        fma2(accP[p][3], ap, b3d);
                    }
                } else {
                    #pragma unroll
                    for (int p = 0; p < 4; p++) {
                        u64 ap = ar[p];
                        fma2(accQ[p][0], ap, b0);
                        fma2(accQ[p][1], ap, b1d);
                        fma2(accQ[p][2], ap, b2d);
                        fma2(accQ[p][3], ap, b3d);
                    }
                }
            }
            __syncthreads();
        }
    }

    #pragma unroll
    for (int p = 0; p < 4; p++) {
        int gb0 = bb * 128 + ty * 8 + p * 2;
        #pragma unroll
        for (int j = 0; j < 4; j++) {
            float2 vp = upk2(accP[p][j]);
            float2 vq = upk2(accQ[p][j]);
            int a = tx * 4 + j;
            g_P[((size_t)gb0 * TT + t) * AA + a]       = vp.x;
            g_P[((size_t)(gb0 + 1) * TT + t) * AA + a] = vp.y;
            g_Q[((size_t)gb0 * TT + t) * AA + a]       = vq.x;
            g_Q[((size_t)(gb0 + 1) * TT + t) * AA + a] = vq.y;
        }
    }
}

// ---------------- K4B: combine P + reverse-gathered Q, bias, tanh ----------------
__global__ void k4b_combine(const int* __restrict__ au, const float* __restrict__ bc,
                            float* __restrict__ out) {
    int idx = blockIdx.x * 256 + threadIdx.x;    // over BT*AA = 4M
    int b = idx >> 11;
    int r = idx & 2047;
    int t = r >> 6;
    int a = r & 63;
    int a0 = au[b];
    int rev = (t < a0) ? (a0 - 1 - t) : t;
    float v = g_P[idx] + g_Q[((size_t)b * TT + rev) * AA + a] + bc[a];
    out[idx] = ftanh(v);
}

// ---------------- launch ----------------
extern "C" void kernel_launch(void* const* d_in, const int* in_sizes, int n_in,
                              void* d_out, int out_size) {
    int s = (n_in >= 18) ? 1 : 0;
    const float* ud  = (const float*)d_in[0];
    const int*   au  = (const int*)  d_in[2];
    const float* g1  = (const float*)d_in[3 + s];
    const float* b1  = (const float*)d_in[4 + s];
    const float* Wd  = (const float*)d_in[5 + s];
    const float* bd  = (const float*)d_in[6 + s];
    const float* g2  = (const float*)d_in[7 + s];
    const float* b2  = (const float*)d_in[8 + s];
    const float* Wfw = (const float*)d_in[9 + s];
    const float* bfw = (const float*)d_in[10 + s];
    const float* Wbw = (const float*)d_in[11 + s];
    const float* bbw = (const float*)d_in[12 + s];
    const float* g3  = (const float*)d_in[13 + s];
    const float* b3  = (const float*)d_in[14 + s];
    const float* Wc  = (const float*)d_in[15 + s];
    const float* bc  = (const float*)d_in[16 + s];
    float* out = (float*)d_out;

    const int K2_SMEM = 1024 + 3 * 49152 + 66048 + 17408;   // 231936 bytes
    cudaFuncSetAttribute(k2p_persist, cudaFuncAttributeMaxDynamicSharedMemorySize, K2_SMEM);

    kp_w<<<(2 * KIN * G4) / 256, 256>>>(Wfw, Wbw);
    k0_rowstats<<<BT / 8, dim3(32, 8)>>>(ud);
    k1_dense<<<BT / 128, 256>>>(ud, g1, b1, Wd, bd, g2, b2);
    k2p_persist<<<dim3(16, 4, 2), 512, K2_SMEM>>>(bfw, bbw, au);
    k3a_part<<<dim3(8, 16), 256>>>();
    k3b_reduce<<<8, 256>>>();
    k4a_gemm<<<dim3(16, 32), 256>>>(g3, b3, Wc);
    k4b_combine<<<(BT * AA) / 256, 256>>>(au, bc, out);
}